// round 6
// baseline (speedup 1.0000x reference)
#include <cuda_runtime.h>

#define NH   12
#define HD   64
#define NSEQ 2048
#define NB   2
#define DIN  768
#define PADA 68   // attention smem row stride (== 4 mod 32 -> conflict-free frags)
#define PADG 36   // gemm smem row stride
#define MASKV (-3e30f)   // must be well below MINIT so masked rows underflow to 0
#define MINIT (-1e30f)

// scratch: h = x @ Wq^T (pre-rounded to tf32), laid out [b][head][q][d]
__device__ float g_h[NB * NH * NSEQ * HD];

__device__ __forceinline__ unsigned f2tf(float f) {
    unsigned u; asm("cvt.rna.tf32.f32 %0, %1;" : "=r"(u) : "f"(f)); return u;
}
__device__ __forceinline__ void mma8(float d[4], const unsigned a[4], const unsigned b[2]) {
    asm volatile(
        "mma.sync.aligned.m16n8k8.row.col.f32.tf32.tf32.f32 "
        "{%0,%1,%2,%3},{%4,%5,%6,%7},{%8,%9},{%0,%1,%2,%3};"
        : "+f"(d[0]), "+f"(d[1]), "+f"(d[2]), "+f"(d[3])
        : "r"(a[0]), "r"(a[1]), "r"(a[2]), "r"(a[3]), "r"(b[0]), "r"(b[1]));
}

// ---------------------------------------------------------------------------
// Kernel 1: qkv projection  y[m][n] = sum_k x[m][k] * Wq[n][k]  via tf32 mma,
// scattered (tf32-rounded) into g_h[b][head][q][d].
// grid (32, 12): 128-row m tiles x one 64-col head. block 256 (8 warps 4x2).
// ---------------------------------------------------------------------------
__global__ __launch_bounds__(256) void qkv_gemm(const float* __restrict__ x,
                                                const float* __restrict__ Wq) {
    __shared__ unsigned As[128 * PADG];
    __shared__ unsigned Bs[64 * PADG];
    const int tid = threadIdx.x;
    const int lane = tid & 31, wid = tid >> 5;
    const int gid = lane >> 2, tig = lane & 3;
    const int wm = (wid & 3) * 32, wn = (wid >> 2) * 32;
    const int m0 = blockIdx.x * 128;
    const int head = blockIdx.y;
    const int n0 = head * 64;

    float acc[2][4][4] = {};

    for (int k0 = 0; k0 < DIN; k0 += 32) {
        #pragma unroll
        for (int i = 0; i < 4; ++i) {                 // A tile 128x32
            int idx = tid + i * 256;                  // float4 idx (1024)
            int row = idx >> 3, c4 = (idx & 7) * 4;
            float4 v = *(const float4*)&x[(size_t)(m0 + row) * DIN + k0 + c4];
            unsigned* d = &As[row * PADG + c4];
            d[0] = f2tf(v.x); d[1] = f2tf(v.y); d[2] = f2tf(v.z); d[3] = f2tf(v.w);
        }
        #pragma unroll
        for (int i = 0; i < 2; ++i) {                 // B tile 64x32
            int idx = tid + i * 256;                  // float4 idx (512)
            int row = idx >> 3, c4 = (idx & 7) * 4;
            float4 v = *(const float4*)&Wq[(size_t)(n0 + row) * DIN + k0 + c4];
            unsigned* d = &Bs[row * PADG + c4];
            d[0] = f2tf(v.x); d[1] = f2tf(v.y); d[2] = f2tf(v.z); d[3] = f2tf(v.w);
        }
        __syncthreads();
        #pragma unroll
        for (int k8 = 0; k8 < 4; ++k8) {
            unsigned a[2][4], b[4][2];
            #pragma unroll
            for (int mi = 0; mi < 2; ++mi) {
                int r = wm + mi * 16;
                a[mi][0] = As[(r + gid    ) * PADG + k8 * 8 + tig    ];
                a[mi][1] = As[(r + gid + 8) * PADG + k8 * 8 + tig    ];
                a[mi][2] = As[(r + gid    ) * PADG + k8 * 8 + tig + 4];
                a[mi][3] = As[(r + gid + 8) * PADG + k8 * 8 + tig + 4];
            }
            #pragma unroll
            for (int ni = 0; ni < 4; ++ni) {
                int c = wn + ni * 8;
                b[ni][0] = Bs[(c + gid) * PADG + k8 * 8 + tig    ];
                b[ni][1] = Bs[(c + gid) * PADG + k8 * 8 + tig + 4];
            }
            #pragma unroll
            for (int mi = 0; mi < 2; ++mi)
                #pragma unroll
                for (int ni = 0; ni < 4; ++ni)
                    mma8(acc[mi][ni], a[mi], b[ni]);
        }
        __syncthreads();
    }

    // epilogue: tf32-round and scatter to g_h[b][head][q][d]
    #pragma unroll
    for (int mi = 0; mi < 2; ++mi) {
        #pragma unroll
        for (int h = 0; h < 2; ++h) {
            int m = m0 + wm + mi * 16 + gid + h * 8;
            int b = m >> 11, q = m & 2047;
            float* dst = &g_h[((size_t)(b * NH + head) * NSEQ + q) * HD];
            #pragma unroll
            for (int ni = 0; ni < 4; ++ni) {
                int d = wn + ni * 8 + 2 * tig;
                float2 v;
                v.x = __uint_as_float(f2tf(acc[mi][ni][2 * h + 0]));
                v.y = __uint_as_float(f2tf(acc[mi][ni][2 * h + 1]));
                *(float2*)&dst[d] = v;
            }
        }
    }
}

// ---------------------------------------------------------------------------
// Kernel 2: fused causal flash attention (tf32 mma). K tile == V tile.
// Phase-overlapped mainloop: iteration kt interleaves O(kt) += P·V with
// S(kt+1) = Q·K — two independent MMA/LDS chains for 2x per-warp ILP.
// grid (16 q-tiles of 128, 24 bh), block 256 (8 warps, 16 q-rows each).
// Output layout out[bh][d][q].
// ---------------------------------------------------------------------------
__device__ __forceinline__ void load_ktile_async(float* kbuf, const float* src,
                                                 int tid) {
    #pragma unroll
    for (int i = 0; i < 4; ++i) {
        int idx = tid + i * 256;                   // float4 idx (1024)
        int row = idx >> 4, c4 = (idx & 15) * 4;
        unsigned dst = (unsigned)__cvta_generic_to_shared(&kbuf[row * PADA + c4]);
        asm volatile("cp.async.cg.shared.global [%0], [%1], 16;"
                     :: "r"(dst), "l"(src + (size_t)row * HD + c4));
    }
    asm volatile("cp.async.commit_group;");
}

__global__ __launch_bounds__(256, 2) void attn_kernel(float* __restrict__ out) {
    extern __shared__ float smem[];
    float* Qs  = smem;                      // 128*PADA
    float* Kb0 = smem + 128 * PADA;         // 64*PADA
    float* Kb1 = smem + 192 * PADA;         // 64*PADA
    float* Ps  = smem + 256 * PADA;         // 128*PADA

    const int tid = threadIdx.x;
    const int lane = tid & 31, wid = tid >> 5;
    const int gid = lane >> 2, tig = lane & 3;
    const int qt = 15 - blockIdx.x;         // heavy tiles scheduled first
    const int bh = blockIdx.y;
    const float* hbase = &g_h[(size_t)bh * NSEQ * HD];
    const int q0 = qt * 128;
    const int r0 = wid * 16;
    const int nkt = 2 * qt + 2;             // >= 2 always

    // prologue: async K0, K1; regular Q loads overlap
    load_ktile_async(Kb0, hbase, tid);
    load_ktile_async(Kb1, hbase + 64 * HD, tid);
    #pragma unroll
    for (int i = 0; i < 8; ++i) {           // Q tile 128x64
        int idx = tid + i * 256;            // float4 idx (2048)
        int row = idx >> 4, c4 = (idx & 15) * 4;
        *(float4*)&Qs[row * PADA + c4] =
            *(const float4*)&hbase[(size_t)(q0 + row) * HD + c4];
    }
    asm volatile("cp.async.wait_group 1;"); // K0 arrived (K1 may be in flight)
    __syncthreads();

    float o[8][4] = {};
    float s[8][4] = {};
    float mrow[2] = {MINIT, MINIT};
    float lrow[2] = {0.f, 0.f};
    // base-2 softmax: scale = (1/sqrt(64)) * log2(e)
    const float sc2 = 0.18033688011112042f;

    // ---- S(0) = Q K0^T (raw, unscaled) ----
    #pragma unroll
    for (int k8 = 0; k8 < 8; ++k8) {
        unsigned a[4];
        a[0] = __float_as_uint(Qs[(r0 + gid    ) * PADA + k8 * 8 + tig    ]);
        a[1] = __float_as_uint(Qs[(r0 + gid + 8) * PADA + k8 * 8 + tig    ]);
        a[2] = __float_as_uint(Qs[(r0 + gid    ) * PADA + k8 * 8 + tig + 4]);
        a[3] = __float_as_uint(Qs[(r0 + gid + 8) * PADA + k8 * 8 + tig + 4]);
        #pragma unroll
        for (int ni = 0; ni < 8; ++ni) {
            unsigned b[2];
            b[0] = __float_as_uint(Kb0[(ni * 8 + gid) * PADA + k8 * 8 + tig    ]);
            b[1] = __float_as_uint(Kb0[(ni * 8 + gid) * PADA + k8 * 8 + tig + 4]);
            mma8(s[ni], a, b);
        }
    }

    for (int kt = 0; kt < nkt; ++kt) {
        const bool have_next = (kt + 1 < nkt);
        float* Kcur = (kt & 1) ? Kb1 : Kb0;
        float* Knxt = (kt & 1) ? Kb0 : Kb1;

        // ---- softmax on raw S(kt): scale (base-2) + causal mask ----
        if (kt >= 2 * qt) {
            int qg0 = q0 + r0 + gid, qg1 = qg0 + 8;
            #pragma unroll
            for (int ni = 0; ni < 8; ++ni) {
                int kg = kt * 64 + ni * 8 + 2 * tig;
                s[ni][0] = (kg     > qg0) ? MASKV : s[ni][0] * sc2;
                s[ni][1] = (kg + 1 > qg0) ? MASKV : s[ni][1] * sc2;
                s[ni][2] = (kg     > qg1) ? MASKV : s[ni][2] * sc2;
                s[ni][3] = (kg + 1 > qg1) ? MASKV : s[ni][3] * sc2;
            }
        } else {
            #pragma unroll
            for (int ni = 0; ni < 8; ++ni)
                #pragma unroll
                for (int j = 0; j < 4; ++j) s[ni][j] *= sc2;
        }
        #pragma unroll
        for (int h = 0; h < 2; ++h) {
            float mx = MASKV;
            #pragma unroll
            for (int ni = 0; ni < 8; ++ni)
                mx = fmaxf(mx, fmaxf(s[ni][2 * h], s[ni][2 * h + 1]));
            mx = fmaxf(mx, __shfl_xor_sync(0xffffffffu, mx, 1));
            mx = fmaxf(mx, __shfl_xor_sync(0xffffffffu, mx, 2));
            float mn = fmaxf(mrow[h], mx);          // >= MINIT always
            float corr = exp2f(mrow[h] - mn);
            mrow[h] = mn;
            float rs = 0.f;
            #pragma unroll
            for (int ni = 0; ni < 8; ++ni) {
                float p0 = exp2f(s[ni][2 * h    ] - mn);
                float p1 = exp2f(s[ni][2 * h + 1] - mn);
                s[ni][2 * h] = p0; s[ni][2 * h + 1] = p1;
                rs += p0 + p1;
            }
            rs += __shfl_xor_sync(0xffffffffu, rs, 1);
            rs += __shfl_xor_sync(0xffffffffu, rs, 2);
            lrow[h] = lrow[h] * corr + rs;
            #pragma unroll
            for (int ni = 0; ni < 8; ++ni) { o[ni][2 * h] *= corr; o[ni][2 * h + 1] *= corr; }
        }

        // ---- stage P(kt) to smem (warp-private rows), freeing s regs ----
        #pragma unroll
        for (int ni = 0; ni < 8; ++ni) {
            int col = ni * 8 + 2 * tig;
            float2 v0, v1;
            v0.x = __uint_as_float(f2tf(s[ni][0])); v0.y = __uint_as_float(f2tf(s[ni][1]));
            v1.x = __uint_as_float(f2tf(s[ni][2])); v1.y = __uint_as_float(f2tf(s[ni][3]));
            *(float2*)&Ps[(r0 + gid    ) * PADA + col] = v0;
            *(float2*)&Ps[(r0 + gid + 8) * PADA + col] = v1;
        }
        __syncwarp();

        if (have_next) {
            // K(kt+1) complete + visible to all warps before anyone reads Knxt
            asm volatile("cp.async.wait_group 0;");
            __syncthreads();
            // zero s for S(kt+1)
            #pragma unroll
            for (int ni = 0; ni < 8; ++ni)
                #pragma unroll
                for (int j = 0; j < 4; ++j) s[ni][j] = 0.f;

            // ---- fused: O(kt) += P·Kcur  interleaved with  S(kt+1) = Q·Knxt ----
            #pragma unroll
            for (int k8 = 0; k8 < 8; ++k8) {
                unsigned pa[4], qa[4];
                pa[0] = __float_as_uint(Ps[(r0 + gid    ) * PADA + k8 * 8 + tig    ]);
                pa[1] = __float_as_uint(Ps[(r0 + gid + 8) * PADA + k8 * 8 + tig    ]);
                pa[2] = __float_as_uint(Ps[(r0 + gid    ) * PADA + k8 * 8 + tig + 4]);
                pa[3] = __float_as_uint(Ps[(r0 + gid + 8) * PADA + k8 * 8 + tig + 4]);
                qa[0] = __float_as_uint(Qs[(r0 + gid    ) * PADA + k8 * 8 + tig    ]);
                qa[1] = __float_as_uint(Qs[(r0 + gid + 8) * PADA + k8 * 8 + tig    ]);
                qa[2] = __float_as_uint(Qs[(r0 + gid    ) * PADA + k8 * 8 + tig + 4]);
                qa[3] = __float_as_uint(Qs[(r0 + gid + 8) * PADA + k8 * 8 + tig + 4]);
                #pragma unroll
                for (int ni = 0; ni < 8; ++ni) {
                    unsigned bo[2], bs[2];
                    bo[0] = __float_as_uint(Kcur[(k8 * 8 + tig    ) * PADA + ni * 8 + gid]);
                    bo[1] = __float_as_uint(Kcur[(k8 * 8 + tig + 4) * PADA + ni * 8 + gid]);
                    mma8(o[ni], pa, bo);
                    bs[0] = __float_as_uint(Knxt[(ni * 8 + gid) * PADA + k8 * 8 + tig    ]);
                    bs[1] = __float_as_uint(Knxt[(ni * 8 + gid) * PADA + k8 * 8 + tig + 4]);
                    mma8(s[ni], qa, bs);
                }
            }

            // all reads of Kcur done -> safe to overwrite with K(kt+2)
            __syncthreads();
            if (kt + 2 < nkt)
                load_ktile_async(Kcur, hbase + (size_t)(kt + 2) * 64 * HD, tid);
        } else {
            // last tile: O only
            #pragma unroll
            for (int k8 = 0; k8 < 8; ++k8) {
                unsigned pa[4];
                pa[0] = __float_as_uint(Ps[(r0 + gid    ) * PADA + k8 * 8 + tig    ]);
                pa[1] = __float_as_uint(Ps[(r0 + gid + 8) * PADA + k8 * 8 + tig    ]);
                pa[2] = __float_as_uint(Ps[(r0 + gid    ) * PADA + k8 * 8 + tig + 4]);
                pa[3] = __float_as_uint(Ps[(r0 + gid + 8) * PADA + k8 * 8 + tig + 4]);
                #pragma unroll
                for (int ni = 0; ni < 8; ++ni) {
                    unsigned bo[2];
                    bo[0] = __float_as_uint(Kcur[(k8 * 8 + tig    ) * PADA + ni * 8 + gid]);
                    bo[1] = __float_as_uint(Kcur[(k8 * 8 + tig + 4) * PADA + ni * 8 + gid]);
                    mma8(o[ni], pa, bo);
                }
            }
        }
    }

    // epilogue: normalize, transpose through smem, coalesced store out[bh][d][q]
    __syncthreads();
    float* Os = smem;                       // 64 x 132 staging
    float inv0 = 1.0f / lrow[0], inv1 = 1.0f / lrow[1];
    #pragma unroll
    for (int ni = 0; ni < 8; ++ni) {
        int d = ni * 8 + 2 * tig;
        Os[(d    ) * 132 + r0 + gid    ] = o[ni][0] * inv0;
        Os[(d + 1) * 132 + r0 + gid    ] = o[ni][1] * inv0;
        Os[(d    ) * 132 + r0 + gid + 8] = o[ni][2] * inv1;
        Os[(d + 1) * 132 + r0 + gid + 8] = o[ni][3] * inv1;
    }
    __syncthreads();
    float* obase = out + (size_t)bh * HD * NSEQ + q0;
    #pragma unroll
    for (int i = 0; i < 8; ++i) {           // 2048 float4s = full 64x128 tile
        int idx = tid + i * 256;
        int d = idx >> 5, q4 = (idx & 31) * 4;
        *(float4*)&obase[(size_t)d * NSEQ + q4] = *(float4*)&Os[d * 132 + q4];
    }
}

// ---------------------------------------------------------------------------
extern "C" void kernel_launch(void* const* d_in, const int* in_sizes, int n_in,
                              void* d_out, int out_size) {
    const float* x  = (const float*)d_in[0];
    const float* Wq = (const float*)d_in[1];
    float* out = (float*)d_out;

    const int attn_smem = 384 * PADA * sizeof(float);   // 104448 B
    cudaFuncSetAttribute(attn_kernel, cudaFuncAttributeMaxDynamicSharedMemorySize,
                         attn_smem);

    qkv_gemm<<<dim3(32, 12), 256>>>(x, Wq);
    attn_kernel<<<dim3(16, 24), 256, attn_smem>>>(out);
}

// round 8
// speedup vs baseline: 1.1722x; 1.1722x over previous
#include <cuda_runtime.h>

#define NH   12
#define HD   64
#define NSEQ 2048
#define NB   2
#define DIN  768
#define PADA 68   // attention smem row stride (== 4 mod 32 -> conflict-free frags)
#define PADG 36   // gemm smem row stride
#define MASKV (-3e30f)   // must be well below MINIT so masked rows underflow to 0
#define MINIT (-1e30f)

// scratch: h = x @ Wq^T (pre-rounded to tf32), laid out [b][head][q][d]
__device__ float g_h[NB * NH * NSEQ * HD];

__device__ __forceinline__ unsigned f2tf(float f) {
    unsigned u; asm("cvt.rna.tf32.f32 %0, %1;" : "=r"(u) : "f"(f)); return u;
}
__device__ __forceinline__ void mma8(float d[4], const unsigned a[4], const unsigned b[2]) {
    asm volatile(
        "mma.sync.aligned.m16n8k8.row.col.f32.tf32.tf32.f32 "
        "{%0,%1,%2,%3},{%4,%5,%6,%7},{%8,%9},{%0,%1,%2,%3};"
        : "+f"(d[0]), "+f"(d[1]), "+f"(d[2]), "+f"(d[3])
        : "r"(a[0]), "r"(a[1]), "r"(a[2]), "r"(a[3]), "r"(b[0]), "r"(b[1]));
}

// ---------------------------------------------------------------------------
// Kernel 1: qkv projection  y[m][n] = sum_k x[m][k] * Wq[n][k]  via tf32 mma,
// cp.async double-buffered; tf32 rounding applied at fragment-load time.
// grid (32, 12): 128-row m tiles x one 64-col head. block 256 (8 warps 4x2).
// smem (dynamic): 2 x (128+64) x PADG floats = 55296 B.
// ---------------------------------------------------------------------------
__device__ __forceinline__ void gemm_prefetch(float* As, float* Bs,
                                              const float* x, const float* Wq,
                                              int m0, int n0, int k0, int tid) {
    #pragma unroll
    for (int i = 0; i < 4; ++i) {                 // A tile 128x32 (1024 float4)
        int idx = tid + i * 256;
        int row = idx >> 3, c4 = (idx & 7) * 4;
        unsigned dst = (unsigned)__cvta_generic_to_shared(&As[row * PADG + c4]);
        asm volatile("cp.async.cg.shared.global [%0], [%1], 16;"
                     :: "r"(dst), "l"(&x[(size_t)(m0 + row) * DIN + k0 + c4]));
    }
    #pragma unroll
    for (int i = 0; i < 2; ++i) {                 // B tile 64x32 (512 float4)
        int idx = tid + i * 256;
        int row = idx >> 3, c4 = (idx & 7) * 4;
        unsigned dst = (unsigned)__cvta_generic_to_shared(&Bs[row * PADG + c4]);
        asm volatile("cp.async.cg.shared.global [%0], [%1], 16;"
                     :: "r"(dst), "l"(&Wq[(size_t)(n0 + row) * DIN + k0 + c4]));
    }
    asm volatile("cp.async.commit_group;");
}

__global__ __launch_bounds__(256) void qkv_gemm(const float* __restrict__ x,
                                                const float* __restrict__ Wq) {
    extern __shared__ float gsm[];
    float* Asb[2] = {gsm, gsm + 128 * PADG};
    float* Bsb[2] = {gsm + 256 * PADG, gsm + 320 * PADG};

    const int tid = threadIdx.x;
    const int lane = tid & 31, wid = tid >> 5;
    const int gid = lane >> 2, tig = lane & 3;
    const int wm = (wid & 3) * 32, wn = (wid >> 2) * 32;
    const int m0 = blockIdx.x * 128;
    const int head = blockIdx.y;
    const int n0 = head * 64;
    const int NKK = DIN / 32;                     // 24

    float acc[2][4][4] = {};

    gemm_prefetch(Asb[0], Bsb[0], x, Wq, m0, n0, 0, tid);

    for (int kk = 0; kk < NKK; ++kk) {
        if (kk + 1 < NKK) {
            gemm_prefetch(Asb[(kk + 1) & 1], Bsb[(kk + 1) & 1],
                          x, Wq, m0, n0, (kk + 1) * 32, tid);
            asm volatile("cp.async.wait_group 1;");
        } else {
            asm volatile("cp.async.wait_group 0;");
        }
        __syncthreads();
        const float* As = Asb[kk & 1];
        const float* Bs = Bsb[kk & 1];

        #pragma unroll
        for (int k8 = 0; k8 < 4; ++k8) {
            unsigned a[2][4], b[4][2];
            #pragma unroll
            for (int mi = 0; mi < 2; ++mi) {
                int r = wm + mi * 16;
                a[mi][0] = f2tf(As[(r + gid    ) * PADG + k8 * 8 + tig    ]);
                a[mi][1] = f2tf(As[(r + gid + 8) * PADG + k8 * 8 + tig    ]);
                a[mi][2] = f2tf(As[(r + gid    ) * PADG + k8 * 8 + tig + 4]);
                a[mi][3] = f2tf(As[(r + gid + 8) * PADG + k8 * 8 + tig + 4]);
            }
            #pragma unroll
            for (int ni = 0; ni < 4; ++ni) {
                int c = wn + ni * 8;
                b[ni][0] = f2tf(Bs[(c + gid) * PADG + k8 * 8 + tig    ]);
                b[ni][1] = f2tf(Bs[(c + gid) * PADG + k8 * 8 + tig + 4]);
            }
            #pragma unroll
            for (int mi = 0; mi < 2; ++mi)
                #pragma unroll
                for (int ni = 0; ni < 4; ++ni)
                    mma8(acc[mi][ni], a[mi], b[ni]);
        }
        __syncthreads();   // compute done before this buffer is refilled
    }

    // epilogue: tf32-round and scatter to g_h[b][head][q][d]
    #pragma unroll
    for (int mi = 0; mi < 2; ++mi) {
        #pragma unroll
        for (int h = 0; h < 2; ++h) {
            int m = m0 + wm + mi * 16 + gid + h * 8;
            int b = m >> 11, q = m & 2047;
            float* dst = &g_h[((size_t)(b * NH + head) * NSEQ + q) * HD];
            #pragma unroll
            for (int ni = 0; ni < 4; ++ni) {
                int d = wn + ni * 8 + 2 * tig;
                float2 v;
                v.x = __uint_as_float(f2tf(acc[mi][ni][2 * h + 0]));
                v.y = __uint_as_float(f2tf(acc[mi][ni][2 * h + 1]));
                *(float2*)&dst[d] = v;
            }
        }
    }
}

// ---------------------------------------------------------------------------
// Kernel 2: fused causal flash attention (tf32 mma). K tile == V tile.
// Work-sorted 1D grid (heaviest 296 blocks form wave 1; wave 2 is qt<=3 stubs).
// Phase-overlapped mainloop; double-buffered cp.async K tiles.
// block 256 (8 warps, 16 q-rows each). Output layout out[bh][d][q].
// ---------------------------------------------------------------------------
__device__ __forceinline__ void load_ktile_async(float* kbuf, const float* src,
                                                 int tid) {
    #pragma unroll
    for (int i = 0; i < 4; ++i) {
        int idx = tid + i * 256;                   // float4 idx (1024)
        int row = idx >> 4, c4 = (idx & 15) * 4;
        unsigned dst = (unsigned)__cvta_generic_to_shared(&kbuf[row * PADA + c4]);
        asm volatile("cp.async.cg.shared.global [%0], [%1], 16;"
                     :: "r"(dst), "l"(src + (size_t)row * HD + c4));
    }
    asm volatile("cp.async.commit_group;");
}

__global__ __launch_bounds__(256, 2) void attn_kernel(float* __restrict__ out) {
    extern __shared__ float smem[];
    float* Qs  = smem;                      // 128*PADA
    float* Kb0 = smem + 128 * PADA;         // 64*PADA
    float* Kb1 = smem + 192 * PADA;         // 64*PADA
    float* Ps  = smem + 256 * PADA;         // 128*PADA

    const int tid = threadIdx.x;
    const int lane = tid & 31, wid = tid >> 5;
    const int gid = lane >> 2, tig = lane & 3;
    // work-sorted mapping: blocks 0..23 are qt=15 (heaviest), then qt=14, ...
    const int qt = 15 - (blockIdx.x / 24);
    const int bh = blockIdx.x % 24;
    const float* hbase = &g_h[(size_t)bh * NSEQ * HD];
    const int q0 = qt * 128;
    const int r0 = wid * 16;
    const int nkt = 2 * qt + 2;             // >= 2 always

    // prologue: async K0, K1; regular Q loads overlap
    load_ktile_async(Kb0, hbase, tid);
    load_ktile_async(Kb1, hbase + 64 * HD, tid);
    #pragma unroll
    for (int i = 0; i < 8; ++i) {           // Q tile 128x64
        int idx = tid + i * 256;            // float4 idx (2048)
        int row = idx >> 4, c4 = (idx & 15) * 4;
        *(float4*)&Qs[row * PADA + c4] =
            *(const float4*)&hbase[(size_t)(q0 + row) * HD + c4];
    }
    asm volatile("cp.async.wait_group 1;"); // K0 arrived (K1 may be in flight)
    __syncthreads();

    float o[8][4] = {};
    float s[8][4] = {};
    float mrow[2] = {MINIT, MINIT};
    float lrow[2] = {0.f, 0.f};
    // base-2 softmax: scale = (1/sqrt(64)) * log2(e)
    const float sc2 = 0.18033688011112042f;

    // ---- S(0) = Q K0^T (raw, unscaled) ----
    #pragma unroll
    for (int k8 = 0; k8 < 8; ++k8) {
        unsigned a[4];
        a[0] = __float_as_uint(Qs[(r0 + gid    ) * PADA + k8 * 8 + tig    ]);
        a[1] = __float_as_uint(Qs[(r0 + gid + 8) * PADA + k8 * 8 + tig    ]);
        a[2] = __float_as_uint(Qs[(r0 + gid    ) * PADA + k8 * 8 + tig + 4]);
        a[3] = __float_as_uint(Qs[(r0 + gid + 8) * PADA + k8 * 8 + tig + 4]);
        #pragma unroll
        for (int ni = 0; ni < 8; ++ni) {
            unsigned b[2];
            b[0] = __float_as_uint(Kb0[(ni * 8 + gid) * PADA + k8 * 8 + tig    ]);
            b[1] = __float_as_uint(Kb0[(ni * 8 + gid) * PADA + k8 * 8 + tig + 4]);
            mma8(s[ni], a, b);
        }
    }

    for (int kt = 0; kt < nkt; ++kt) {
        const bool have_next = (kt + 1 < nkt);
        float* Kcur = (kt & 1) ? Kb1 : Kb0;
        float* Knxt = (kt & 1) ? Kb0 : Kb1;

        // ---- softmax on raw S(kt): scale (base-2) + causal mask ----
        if (kt >= 2 * qt) {
            int qg0 = q0 + r0 + gid, qg1 = qg0 + 8;
            #pragma unroll
            for (int ni = 0; ni < 8; ++ni) {
                int kg = kt * 64 + ni * 8 + 2 * tig;
                s[ni][0] = (kg     > qg0) ? MASKV : s[ni][0] * sc2;
                s[ni][1] = (kg + 1 > qg0) ? MASKV : s[ni][1] * sc2;
                s[ni][2] = (kg     > qg1) ? MASKV : s[ni][2] * sc2;
                s[ni][3] = (kg + 1 > qg1) ? MASKV : s[ni][3] * sc2;
            }
        } else {
            #pragma unroll
            for (int ni = 0; ni < 8; ++ni)
                #pragma unroll
                for (int j = 0; j < 4; ++j) s[ni][j] *= sc2;
        }
        #pragma unroll
        for (int h = 0; h < 2; ++h) {
            float mx = MASKV;
            #pragma unroll
            for (int ni = 0; ni < 8; ++ni)
                mx = fmaxf(mx, fmaxf(s[ni][2 * h], s[ni][2 * h + 1]));
            mx = fmaxf(mx, __shfl_xor_sync(0xffffffffu, mx, 1));
            mx = fmaxf(mx, __shfl_xor_sync(0xffffffffu, mx, 2));
            float mn = fmaxf(mrow[h], mx);          // >= MINIT always
            float corr = exp2f(mrow[h] - mn);
            mrow[h] = mn;
            float rs = 0.f;
            #pragma unroll
            for (int ni = 0; ni < 8; ++ni) {
                float p0 = exp2f(s[ni][2 * h    ] - mn);
                float p1 = exp2f(s[ni][2 * h + 1] - mn);
                s[ni][2 * h] = p0; s[ni][2 * h + 1] = p1;
                rs += p0 + p1;
            }
            rs += __shfl_xor_sync(0xffffffffu, rs, 1);
            rs += __shfl_xor_sync(0xffffffffu, rs, 2);
            lrow[h] = lrow[h] * corr + rs;
            #pragma unroll
            for (int ni = 0; ni < 8; ++ni) { o[ni][2 * h] *= corr; o[ni][2 * h + 1] *= corr; }
        }

        // ---- stage P(kt) to smem (warp-private rows), freeing s regs ----
        #pragma unroll
        for (int ni = 0; ni < 8; ++ni) {
            int col = ni * 8 + 2 * tig;
            float2 v0, v1;
            v0.x = __uint_as_float(f2tf(s[ni][0])); v0.y = __uint_as_float(f2tf(s[ni][1]));
            v1.x = __uint_as_float(f2tf(s[ni][2])); v1.y = __uint_as_float(f2tf(s[ni][3]));
            *(float2*)&Ps[(r0 + gid    ) * PADA + col] = v0;
            *(float2*)&Ps[(r0 + gid + 8) * PADA + col] = v1;
        }
        __syncwarp();

        if (have_next) {
            // K(kt+1) complete + visible to all warps before anyone reads Knxt
            asm volatile("cp.async.wait_group 0;");
            __syncthreads();
            // zero s for S(kt+1)
            #pragma unroll
            for (int ni = 0; ni < 8; ++ni)
                #pragma unroll
                for (int j = 0; j < 4; ++j) s[ni][j] = 0.f;

            // ---- fused: O(kt) += P·Kcur  interleaved with  S(kt+1) = Q·Knxt ----
            #pragma unroll
            for (int k8 = 0; k8 < 8; ++k8) {
                unsigned pa[4], qa[4];
                pa[0] = __float_as_uint(Ps[(r0 + gid    ) * PADA + k8 * 8 + tig    ]);
                pa[1] = __float_as_uint(Ps[(r0 + gid + 8) * PADA + k8 * 8 + tig    ]);
                pa[2] = __float_as_uint(Ps[(r0 + gid    ) * PADA + k8 * 8 + tig + 4]);
                pa[3] = __float_as_uint(Ps[(r0 + gid + 8) * PADA + k8 * 8 + tig + 4]);
                qa[0] = __float_as_uint(Qs[(r0 + gid    ) * PADA + k8 * 8 + tig    ]);
                qa[1] = __float_as_uint(Qs[(r0 + gid + 8) * PADA + k8 * 8 + tig    ]);
                qa[2] = __float_as_uint(Qs[(r0 + gid    ) * PADA + k8 * 8 + tig + 4]);
                qa[3] = __float_as_uint(Qs[(r0 + gid + 8) * PADA + k8 * 8 + tig + 4]);
                #pragma unroll
                for (int ni = 0; ni < 8; ++ni) {
                    unsigned bo[2], bs[2];
                    bo[0] = __float_as_uint(Kcur[(k8 * 8 + tig    ) * PADA + ni * 8 + gid]);
                    bo[1] = __float_as_uint(Kcur[(k8 * 8 + tig + 4) * PADA + ni * 8 + gid]);
                    mma8(o[ni], pa, bo);
                    bs[0] = __float_as_uint(Knxt[(ni * 8 + gid) * PADA + k8 * 8 + tig    ]);
                    bs[1] = __float_as_uint(Knxt[(ni * 8 + gid) * PADA + k8 * 8 + tig + 4]);
                    mma8(s[ni], qa, bs);
                }
            }

            // all reads of Kcur done -> safe to overwrite with K(kt+2)
            __syncthreads();
            if (kt + 2 < nkt)
                load_ktile_async(Kcur, hbase + (size_t)(kt + 2) * 64 * HD, tid);
        } else {
            // last tile: O only
            #pragma unroll
            for (int k8 = 0; k8 < 8; ++k8) {
                unsigned pa[4];
                pa[0] = __float_as_uint(Ps[(r0 + gid    ) * PADA + k8 * 8 + tig    ]);
                pa[1] = __float_as_uint(Ps[(r0 + gid + 8) * PADA + k8 * 8 + tig    ]);
                pa[2] = __float_as_uint(Ps[(r0 + gid    ) * PADA + k8 * 8 + tig + 4]);
                pa[3] = __float_as_uint(Ps[(r0 + gid + 8) * PADA + k8 * 8 + tig + 4]);
                #pragma unroll
                for (int ni = 0; ni < 8; ++ni) {
                    unsigned bo[2];
                    bo[0] = __float_as_uint(Kcur[(k8 * 8 + tig    ) * PADA + ni * 8 + gid]);
                    bo[1] = __float_as_uint(Kcur[(k8 * 8 + tig + 4) * PADA + ni * 8 + gid]);
                    mma8(o[ni], pa, bo);
                }
            }
        }
    }

    // epilogue: normalize, transpose through smem, coalesced store out[bh][d][q]
    __syncthreads();
    float* Os = smem;                       // 64 x 132 staging
    float inv0 = 1.0f / lrow[0], inv1 = 1.0f / lrow[1];
    #pragma unroll
    for (int ni = 0; ni < 8; ++ni) {
        int d = ni * 8 + 2 * tig;
        Os[(d    ) * 132 + r0 + gid    ] = o[ni][0] * inv0;
        Os[(d + 1) * 132 + r0 + gid    ] = o[ni][1] * inv0;
        Os[(d    ) * 132 + r0 + gid + 8] = o[ni][2] * inv1;
        Os[(d + 1) * 132 + r0 + gid + 8] = o[ni][3] * inv1;
    }
    __syncthreads();
    float* obase = out + (size_t)bh * HD * NSEQ + q0;
    #pragma unroll
    for (int i = 0; i < 8; ++i) {           // 2048 float4s = full 64x128 tile
        int idx = tid + i * 256;
        int d = idx >> 5, q4 = (idx & 31) * 4;
        *(float4*)&obase[(size_t)d * NSEQ + q4] = *(float4*)&Os[d * 132 + q4];
    }
}

// ---------------------------------------------------------------------------
extern "C" void kernel_launch(void* const* d_in, const int* in_sizes, int n_in,
                              void* d_out, int out_size) {
    const float* x  = (const float*)d_in[0];
    const float* Wq = (const float*)d_in[1];
    float* out = (float*)d_out;

    const int gemm_smem = 384 * PADG * sizeof(float);   // 55296 B
    const int attn_smem = 384 * PADA * sizeof(float);   // 104448 B
    cudaFuncSetAttribute(qkv_gemm, cudaFuncAttributeMaxDynamicSharedMemorySize,
                         gemm_smem);
    cudaFuncSetAttribute(attn_kernel, cudaFuncAttributeMaxDynamicSharedMemorySize,
                         attn_smem);

    qkv_gemm<<<dim3(32, 12), 256, gemm_smem>>>(x, Wq);
    attn_kernel<<<384, 256, attn_smem>>>(out);
}

// round 9
// speedup vs baseline: 1.3054x; 1.1136x over previous
#include <cuda_runtime.h>

#define NH   12
#define HD   64
#define NSEQ 2048
#define NB   2
#define DIN  768
#define PADA 68   // smem row stride: gid-row-indexed frag loads are conflict-free
#define PADG 36   // gemm smem row stride
#define MASKV (-3e30f)   // well below MINIT so fully-masked rows underflow to 0
#define MINIT (-1e30f)

// scratch: h = x @ Wq^T (pre-rounded to tf32), laid out [b][head][q][d]
__device__ float g_h[NB * NH * NSEQ * HD];

__device__ __forceinline__ unsigned f2tf(float f) {
    unsigned u; asm("cvt.rna.tf32.f32 %0, %1;" : "=r"(u) : "f"(f)); return u;
}
__device__ __forceinline__ void mma8(float d[4], const unsigned a[4], const unsigned b[2]) {
    asm volatile(
        "mma.sync.aligned.m16n8k8.row.col.f32.tf32.tf32.f32 "
        "{%0,%1,%2,%3},{%4,%5,%6,%7},{%8,%9},{%0,%1,%2,%3};"
        : "+f"(d[0]), "+f"(d[1]), "+f"(d[2]), "+f"(d[3])
        : "r"(a[0]), "r"(a[1]), "r"(a[2]), "r"(a[3]), "r"(b[0]), "r"(b[1]));
}

// ---------------------------------------------------------------------------
// Kernel 1: qkv projection  y[m][n] = sum_k x[m][k] * Wq[n][k]  via tf32 mma,
// cp.async double-buffered; tf32 rounding applied at fragment-load time.
// grid (32, 12): 128-row m tiles x one 64-col head. block 256 (8 warps 4x2).
// ---------------------------------------------------------------------------
__device__ __forceinline__ void gemm_prefetch(float* As, float* Bs,
                                              const float* x, const float* Wq,
                                              int m0, int n0, int k0, int tid) {
    #pragma unroll
    for (int i = 0; i < 4; ++i) {                 // A tile 128x32 (1024 float4)
        int idx = tid + i * 256;
        int row = idx >> 3, c4 = (idx & 7) * 4;
        unsigned dst = (unsigned)__cvta_generic_to_shared(&As[row * PADG + c4]);
        asm volatile("cp.async.cg.shared.global [%0], [%1], 16;"
                     :: "r"(dst), "l"(&x[(size_t)(m0 + row) * DIN + k0 + c4]));
    }
    #pragma unroll
    for (int i = 0; i < 2; ++i) {                 // B tile 64x32 (512 float4)
        int idx = tid + i * 256;
        int row = idx >> 3, c4 = (idx & 7) * 4;
        unsigned dst = (unsigned)__cvta_generic_to_shared(&Bs[row * PADG + c4]);
        asm volatile("cp.async.cg.shared.global [%0], [%1], 16;"
                     :: "r"(dst), "l"(&Wq[(size_t)(n0 + row) * DIN + k0 + c4]));
    }
    asm volatile("cp.async.commit_group;");
}

__global__ __launch_bounds__(256) void qkv_gemm(const float* __restrict__ x,
                                                const float* __restrict__ Wq) {
    extern __shared__ float gsm[];
    float* Asb[2] = {gsm, gsm + 128 * PADG};
    float* Bsb[2] = {gsm + 256 * PADG, gsm + 320 * PADG};

    const int tid = threadIdx.x;
    const int lane = tid & 31, wid = tid >> 5;
    const int gid = lane >> 2, tig = lane & 3;
    const int wm = (wid & 3) * 32, wn = (wid >> 2) * 32;
    const int m0 = blockIdx.x * 128;
    const int head = blockIdx.y;
    const int n0 = head * 64;
    const int NKK = DIN / 32;                     // 24

    float acc[2][4][4] = {};

    gemm_prefetch(Asb[0], Bsb[0], x, Wq, m0, n0, 0, tid);

    for (int kk = 0; kk < NKK; ++kk) {
        if (kk + 1 < NKK) {
            gemm_prefetch(Asb[(kk + 1) & 1], Bsb[(kk + 1) & 1],
                          x, Wq, m0, n0, (kk + 1) * 32, tid);
            asm volatile("cp.async.wait_group 1;");
        } else {
            asm volatile("cp.async.wait_group 0;");
        }
        __syncthreads();
        const float* As = Asb[kk & 1];
        const float* Bs = Bsb[kk & 1];

        #pragma unroll
        for (int k8 = 0; k8 < 4; ++k8) {
            unsigned a[2][4], b[4][2];
            #pragma unroll
            for (int mi = 0; mi < 2; ++mi) {
                int r = wm + mi * 16;
                a[mi][0] = f2tf(As[(r + gid    ) * PADG + k8 * 8 + tig    ]);
                a[mi][1] = f2tf(As[(r + gid + 8) * PADG + k8 * 8 + tig    ]);
                a[mi][2] = f2tf(As[(r + gid    ) * PADG + k8 * 8 + tig + 4]);
                a[mi][3] = f2tf(As[(r + gid + 8) * PADG + k8 * 8 + tig + 4]);
            }
            #pragma unroll
            for (int ni = 0; ni < 4; ++ni) {
                int c = wn + ni * 8;
                b[ni][0] = f2tf(Bs[(c + gid) * PADG + k8 * 8 + tig    ]);
                b[ni][1] = f2tf(Bs[(c + gid) * PADG + k8 * 8 + tig + 4]);
            }
            #pragma unroll
            for (int mi = 0; mi < 2; ++mi)
                #pragma unroll
                for (int ni = 0; ni < 4; ++ni)
                    mma8(acc[mi][ni], a[mi], b[ni]);
        }
        __syncthreads();   // compute done before this buffer is refilled
    }

    // epilogue: tf32-round and scatter to g_h[b][head][q][d]
    #pragma unroll
    for (int mi = 0; mi < 2; ++mi) {
        #pragma unroll
        for (int h = 0; h < 2; ++h) {
            int m = m0 + wm + mi * 16 + gid + h * 8;
            int b = m >> 11, q = m & 2047;
            float* dst = &g_h[((size_t)(b * NH + head) * NSEQ + q) * HD];
            #pragma unroll
            for (int ni = 0; ni < 4; ++ni) {
                int d = wn + ni * 8 + 2 * tig;
                float2 v;
                v.x = __uint_as_float(f2tf(acc[mi][ni][2 * h + 0]));
                v.y = __uint_as_float(f2tf(acc[mi][ni][2 * h + 1]));
                *(float2*)&dst[d] = v;
            }
        }
    }
}

// ---------------------------------------------------------------------------
// Kernel 2: fused causal flash attention (tf32 mma). K tile == V tile.
// Per tile: S = Q·K^T from K (row-major), in-smem transpose K -> KT, then
// O += P·V from KT so BOTH GEMMs' B-loads are gid-row-indexed = conflict-free.
// Single K buffer; next-tile cp.async issued after the transpose barrier so it
// hides under P-staging + O-phase. Work-sorted 1D grid.
// block 256 (8 warps, 16 q-rows each). Output layout out[bh][d][q].
// ---------------------------------------------------------------------------
__device__ __forceinline__ void load_ktile_async(float* kbuf, const float* src,
                                                 int tid) {
    #pragma unroll
    for (int i = 0; i < 4; ++i) {
        int idx = tid + i * 256;                   // float4 idx (1024)
        int row = idx >> 4, c4 = (idx & 15) * 4;
        unsigned dst = (unsigned)__cvta_generic_to_shared(&kbuf[row * PADA + c4]);
        asm volatile("cp.async.cg.shared.global [%0], [%1], 16;"
                     :: "r"(dst), "l"(src + (size_t)row * HD + c4));
    }
    asm volatile("cp.async.commit_group;");
}

__global__ __launch_bounds__(256, 2) void attn_kernel(float* __restrict__ out) {
    extern __shared__ float smem[];
    float* Qs  = smem;                      // 128*PADA
    float* Ks  = smem + 128 * PADA;         // 64*PADA   K  (row-major [key][d])
    float* KTs = smem + 192 * PADA;         // 64*PADA   KT ([d][key])
    float* Ps  = smem + 256 * PADA;         // 128*PADA

    const int tid = threadIdx.x;
    const int lane = tid & 31, wid = tid >> 5;
    const int gid = lane >> 2, tig = lane & 3;
    // work-sorted mapping: blocks 0..23 are qt=15 (heaviest), then qt=14, ...
    const int qt = 15 - ((int)blockIdx.x / 24);
    const int bh = (int)blockIdx.x % 24;
    const float* hbase = &g_h[(size_t)bh * NSEQ * HD];
    const int q0 = qt * 128;
    const int r0 = wid * 16;
    const int nkt = 2 * qt + 2;

    // transpose assignment: thread owns column d, 16 keys starting at tk0
    const int td  = tid & 63;
    const int tk0 = (tid >> 6) * 16;

    // prologue: async K(0); regular Q loads overlap
    load_ktile_async(Ks, hbase, tid);
    #pragma unroll
    for (int i = 0; i < 8; ++i) {           // Q tile 128x64
        int idx = tid + i * 256;            // float4 idx (2048)
        int row = idx >> 4, c4 = (idx & 15) * 4;
        *(float4*)&Qs[row * PADA + c4] =
            *(const float4*)&hbase[(size_t)(q0 + row) * HD + c4];
    }

    float o[8][4] = {};
    float mrow[2] = {MINIT, MINIT};
    float lrow[2] = {0.f, 0.f};
    // base-2 softmax: scale = (1/sqrt(64)) * log2(e)
    const float sc2 = 0.18033688011112042f;

    for (int kt = 0; kt < nkt; ++kt) {
        // K(kt) arrived; prev-iter readers of Ks/KTs/Ps done
        asm volatile("cp.async.wait_group 0;");
        __syncthreads();

        // ---- S = Q K^T (from row-major K; B rows gid-indexed: conflict-free) ----
        float s[8][4] = {};
        #pragma unroll
        for (int k8 = 0; k8 < 8; ++k8) {
            unsigned a[4];
            a[0] = __float_as_uint(Qs[(r0 + gid    ) * PADA + k8 * 8 + tig    ]);
            a[1] = __float_as_uint(Qs[(r0 + gid + 8) * PADA + k8 * 8 + tig    ]);
            a[2] = __float_as_uint(Qs[(r0 + gid    ) * PADA + k8 * 8 + tig + 4]);
            a[3] = __float_as_uint(Qs[(r0 + gid + 8) * PADA + k8 * 8 + tig + 4]);
            #pragma unroll
            for (int ni = 0; ni < 8; ++ni) {
                unsigned b[2];
                b[0] = __float_as_uint(Ks[(ni * 8 + gid) * PADA + k8 * 8 + tig    ]);
                b[1] = __float_as_uint(Ks[(ni * 8 + gid) * PADA + k8 * 8 + tig + 4]);
                mma8(s[ni], a, b);
            }
        }

        // ---- transpose K -> KT (overlaps S-MMA latency; conflict-free both ways)
        {
            float v[16];
            #pragma unroll
            for (int i = 0; i < 16; ++i)
                v[i] = Ks[(tk0 + i) * PADA + td];
            #pragma unroll
            for (int j = 0; j < 4; ++j)
                *(float4*)&KTs[td * PADA + tk0 + 4 * j] =
                    make_float4(v[4 * j], v[4 * j + 1], v[4 * j + 2], v[4 * j + 3]);
        }

        // ---- scale (base-2) + causal mask on S ----
        if (kt >= 2 * qt) {
            int qg0 = q0 + r0 + gid, qg1 = qg0 + 8;
            #pragma unroll
            for (int ni = 0; ni < 8; ++ni) {
                int kg = kt * 64 + ni * 8 + 2 * tig;
                s[ni][0] = (kg     > qg0) ? MASKV : s[ni][0] * sc2;
                s[ni][1] = (kg + 1 > qg0) ? MASKV : s[ni][1] * sc2;
                s[ni][2] = (kg     > qg1) ? MASKV : s[ni][2] * sc2;
                s[ni][3] = (kg + 1 > qg1) ? MASKV : s[ni][3] * sc2;
            }
        } else {
            #pragma unroll
            for (int ni = 0; ni < 8; ++ni)
                #pragma unroll
                for (int j = 0; j < 4; ++j) s[ni][j] *= sc2;
        }

        // ---- online softmax in base 2 (row h: regs 2h,2h+1; quads share rows) ----
        #pragma unroll
        for (int h = 0; h < 2; ++h) {
            float mx = MASKV;
            #pragma unroll
            for (int ni = 0; ni < 8; ++ni)
                mx = fmaxf(mx, fmaxf(s[ni][2 * h], s[ni][2 * h + 1]));
            mx = fmaxf(mx, __shfl_xor_sync(0xffffffffu, mx, 1));
            mx = fmaxf(mx, __shfl_xor_sync(0xffffffffu, mx, 2));
            float mn = fmaxf(mrow[h], mx);          // >= MINIT always
            float corr = exp2f(mrow[h] - mn);
            mrow[h] = mn;
            float rs = 0.f;
            #pragma unroll
            for (int ni = 0; ni < 8; ++ni) {
                float p0 = exp2f(s[ni][2 * h    ] - mn);
                float p1 = exp2f(s[ni][2 * h + 1] - mn);
                s[ni][2 * h] = p0; s[ni][2 * h + 1] = p1;
                rs += p0 + p1;
            }
            rs += __shfl_xor_sync(0xffffffffu, rs, 1);
            rs += __shfl_xor_sync(0xffffffffu, rs, 2);
            lrow[h] = lrow[h] * corr + rs;
            #pragma unroll
            for (int ni = 0; ni < 8; ++ni) { o[ni][2 * h] *= corr; o[ni][2 * h + 1] *= corr; }
        }

        // ---- stage P to smem (warp-private rows) ----
        #pragma unroll
        for (int ni = 0; ni < 8; ++ni) {
            int col = ni * 8 + 2 * tig;
            float2 v0, v1;
            v0.x = __uint_as_float(f2tf(s[ni][0])); v0.y = __uint_as_float(f2tf(s[ni][1]));
            v1.x = __uint_as_float(f2tf(s[ni][2])); v1.y = __uint_as_float(f2tf(s[ni][3]));
            *(float2*)&Ps[(r0 + gid    ) * PADA + col] = v0;
            *(float2*)&Ps[(r0 + gid + 8) * PADA + col] = v1;
        }
        __syncwarp();

        // KT fully written + all transpose reads of Ks done -> prefetch K(kt+1)
        __syncthreads();
        if (kt + 1 < nkt)
            load_ktile_async(Ks, hbase + (size_t)(kt + 1) * 64 * HD, tid);

        // ---- O += P @ V from KT (B rows gid-indexed: conflict-free) ----
        #pragma unroll
        for (int k8 = 0; k8 < 8; ++k8) {
            unsigned pa[4];
            pa[0] = __float_as_uint(Ps[(r0 + gid    ) * PADA + k8 * 8 + tig    ]);
            pa[1] = __float_as_uint(Ps[(r0 + gid + 8) * PADA + k8 * 8 + tig    ]);
            pa[2] = __float_as_uint(Ps[(r0 + gid    ) * PADA + k8 * 8 + tig + 4]);
            pa[3] = __float_as_uint(Ps[(r0 + gid + 8) * PADA + k8 * 8 + tig + 4]);
            #pragma unroll
            for (int ni = 0; ni < 8; ++ni) {
                unsigned bo[2];
                bo[0] = __float_as_uint(KTs[(ni * 8 + gid) * PADA + k8 * 8 + tig    ]);
                bo[1] = __float_as_uint(KTs[(ni * 8 + gid) * PADA + k8 * 8 + tig + 4]);
                mma8(o[ni], pa, bo);
            }
        }
    }

    // epilogue: normalize, transpose through smem, coalesced store out[bh][d][q]
    __syncthreads();
    float* Os = smem;                       // 64 x 132 staging
    float inv0 = 1.0f / lrow[0], inv1 = 1.0f / lrow[1];
    #pragma unroll
    for (int ni = 0; ni < 8; ++ni) {
        int d = ni * 8 + 2 * tig;
        Os[(d    ) * 132 + r0 + gid    ] = o[ni][0] * inv0;
        Os[(d + 1) * 132 + r0 + gid    ] = o[ni][1] * inv0;
        Os[(d    ) * 132 + r0 + gid + 8] = o[ni][2] * inv1;
        Os[(d + 1) * 132 + r0 + gid + 8] = o[ni][3] * inv1;
    }
    __syncthreads();
    float* obase = out + (size_t)bh * HD * NSEQ + q0;
    #pragma unroll
    for (int i = 0; i < 8; ++i) {           // 2048 float4s = full 64x128 tile
        int idx = tid + i * 256;
        int d = idx >> 5, q4 = (idx & 31) * 4;
        *(float4*)&obase[(size_t)d * NSEQ + q4] = *(float4*)&Os[d * 132 + q4];
    }
}

// ---------------------------------------------------------------------------
extern "C" void kernel_launch(void* const* d_in, const int* in_sizes, int n_in,
                              void* d_out, int out_size) {
    const float* x  = (const float*)d_in[0];
    const float* Wq = (const float*)d_in[1];
    float* out = (float*)d_out;

    const int gemm_smem = 384 * PADG * sizeof(float);   // 55296 B
    const int attn_smem = 384 * PADA * sizeof(float);   // 104448 B
    cudaFuncSetAttribute(qkv_gemm, cudaFuncAttributeMaxDynamicSharedMemorySize,
                         gemm_smem);
    cudaFuncSetAttribute(attn_kernel, cudaFuncAttributeMaxDynamicSharedMemorySize,
                         attn_smem);

    qkv_gemm<<<dim3(32, 12), 256, gemm_smem>>>(x, Wq);
    attn_kernel<<<384, 256, attn_smem>>>(out);
}

// round 11
// speedup vs baseline: 1.9298x; 1.4784x over previous
#include <cuda_runtime.h>

#define NH   12
#define HD   64
#define NSEQ 2048
#define NB   2
#define DIN  768
#define PADG 36

// scratch: h = x @ Wq^T (pre-rounded to tf32), laid out [b][head][q][d]
__device__ float g_h[NB * NH * NSEQ * HD];

__device__ __forceinline__ unsigned f2tf(float f) {
    unsigned u; asm("cvt.rna.tf32.f32 %0, %1;" : "=r"(u) : "f"(f)); return u;
}
__device__ __forceinline__ void mma8(float d[4], const unsigned a[4], const unsigned b[2]) {
    asm volatile(
        "mma.sync.aligned.m16n8k8.row.col.f32.tf32.tf32.f32 "
        "{%0,%1,%2,%3},{%4,%5,%6,%7},{%8,%9},{%0,%1,%2,%3};"
        : "+f"(d[0]), "+f"(d[1]), "+f"(d[2]), "+f"(d[3])
        : "r"(a[0]), "r"(a[1]), "r"(a[2]), "r"(a[3]), "r"(b[0]), "r"(b[1]));
}

// ---------------------------------------------------------------------------
// Kernel 1: qkv projection (tf32 fragment mma, cp.async double-buffered)
// ---------------------------------------------------------------------------
__device__ __forceinline__ void gemm_prefetch(float* As, float* Bs,
                                              const float* x, const float* Wq,
                                              int m0, int n0, int k0, int tid) {
    #pragma unroll
    for (int i = 0; i < 4; ++i) {
        int idx = tid + i * 256;
        int row = idx >> 3, c4 = (idx & 7) * 4;
        unsigned dst = (unsigned)__cvta_generic_to_shared(&As[row * PADG + c4]);
        asm volatile("cp.async.cg.shared.global [%0], [%1], 16;"
                     :: "r"(dst), "l"(&x[(size_t)(m0 + row) * DIN + k0 + c4]));
    }
    #pragma unroll
    for (int i = 0; i < 2; ++i) {
        int idx = tid + i * 256;
        int row = idx >> 3, c4 = (idx & 7) * 4;
        unsigned dst = (unsigned)__cvta_generic_to_shared(&Bs[row * PADG + c4]);
        asm volatile("cp.async.cg.shared.global [%0], [%1], 16;"
                     :: "r"(dst), "l"(&Wq[(size_t)(n0 + row) * DIN + k0 + c4]));
    }
    asm volatile("cp.async.commit_group;");
}

__global__ __launch_bounds__(256) void qkv_gemm(const float* __restrict__ x,
                                                const float* __restrict__ Wq) {
    extern __shared__ float gsm[];
    float* Asb[2] = {gsm, gsm + 128 * PADG};
    float* Bsb[2] = {gsm + 256 * PADG, gsm + 320 * PADG};

    const int tid = threadIdx.x;
    const int lane = tid & 31, wid = tid >> 5;
    const int gid = lane >> 2, tig = lane & 3;
    const int wm = (wid & 3) * 32, wn = (wid >> 2) * 32;
    const int m0 = blockIdx.x * 128;
    const int head = blockIdx.y;
    const int n0 = head * 64;
    const int NKK = DIN / 32;

    float acc[2][4][4] = {};
    gemm_prefetch(Asb[0], Bsb[0], x, Wq, m0, n0, 0, tid);

    for (int kk = 0; kk < NKK; ++kk) {
        if (kk + 1 < NKK) {
            gemm_prefetch(Asb[(kk + 1) & 1], Bsb[(kk + 1) & 1],
                          x, Wq, m0, n0, (kk + 1) * 32, tid);
            asm volatile("cp.async.wait_group 1;");
        } else {
            asm volatile("cp.async.wait_group 0;");
        }
        __syncthreads();
        const float* As = Asb[kk & 1];
        const float* Bs = Bsb[kk & 1];

        #pragma unroll
        for (int k8 = 0; k8 < 4; ++k8) {
            unsigned a[2][4], b[4][2];
            #pragma unroll
            for (int mi = 0; mi < 2; ++mi) {
                int r = wm + mi * 16;
                a[mi][0] = f2tf(As[(r + gid    ) * PADG + k8 * 8 + tig    ]);
                a[mi][1] = f2tf(As[(r + gid + 8) * PADG + k8 * 8 + tig    ]);
                a[mi][2] = f2tf(As[(r + gid    ) * PADG + k8 * 8 + tig + 4]);
                a[mi][3] = f2tf(As[(r + gid + 8) * PADG + k8 * 8 + tig + 4]);
            }
            #pragma unroll
            for (int ni = 0; ni < 4; ++ni) {
                int c = wn + ni * 8;
                b[ni][0] = f2tf(Bs[(c + gid) * PADG + k8 * 8 + tig    ]);
                b[ni][1] = f2tf(Bs[(c + gid) * PADG + k8 * 8 + tig + 4]);
            }
            #pragma unroll
            for (int mi = 0; mi < 2; ++mi)
                #pragma unroll
                for (int ni = 0; ni < 4; ++ni)
                    mma8(acc[mi][ni], a[mi], b[ni]);
        }
        __syncthreads();
    }

    #pragma unroll
    for (int mi = 0; mi < 2; ++mi) {
        #pragma unroll
        for (int h = 0; h < 2; ++h) {
            int m = m0 + wm + mi * 16 + gid + h * 8;
            int b = m >> 11, q = m & 2047;
            float* dst = &g_h[((size_t)(b * NH + head) * NSEQ + q) * HD];
            #pragma unroll
            for (int ni = 0; ni < 4; ++ni) {
                int d = wn + ni * 8 + 2 * tig;
                float2 v;
                v.x = __uint_as_float(f2tf(acc[mi][ni][2 * h + 0]));
                v.y = __uint_as_float(f2tf(acc[mi][ni][2 * h + 1]));
                *(float2*)&dst[d] = v;
            }
        }
    }
}

// ---------------------------------------------------------------------------
// Kernel 2: tcgen05 causal flash attention (sm_103a path), with a plain-CUDA
// scalar fallback for the non-'a' PTX compilation pass (never selected at
// runtime -- the driver loads the exact-match sm_103a cubin).
// ---------------------------------------------------------------------------
#define IDESC_TF32 ((1u<<4) | (2u<<7) | (2u<<10) | (8u<<17) | (8u<<24))

#define OFF_TMEM 0
#define OFF_MBS  8
#define OFF_MBO  16
#define OFF_Q    1024                 // 2 slabs x 128 rows x 128B = 32768
#define OFF_K    (OFF_Q  + 32768)     // 2 slabs x 64 x 128B = 16384
#define OFF_KT   (OFF_K  + 16384)     // 16384
#define OFF_P    (OFF_KT + 16384)     // 32768
#define ATTN_SMEM (OFF_P + 32768)     // 99328 B

#if defined(__CUDA_ARCH_FEAT_SM103_ALL) || defined(__CUDA_ARCH_SPECIFIC__) || !defined(__CUDA_ARCH__)
#define HAS_TCGEN05 1
#else
#define HAS_TCGEN05 0
#endif

#if HAS_TCGEN05
__device__ __forceinline__ unsigned sw128(unsigned b) { return b ^ ((b >> 3) & 0x70); }
__device__ __forceinline__ unsigned long long mk_desc(unsigned addr) {
    return 0x4000404000010000ULL | (unsigned long long)((addr >> 4) & 0x3FFF);
}
__device__ __forceinline__ unsigned elect1() {
    unsigned p;
    asm volatile("{\n\t.reg .pred p;\n\telect.sync _|p, 0xFFFFFFFF;\n\t"
                 "selp.b32 %0, 1, 0, p;\n\t}" : "=r"(p));
    return p;
}
__device__ __forceinline__ void mma_tf32_ss(unsigned dtmem, unsigned long long ad,
                                            unsigned long long bd, unsigned en) {
    asm volatile("{\n\t.reg .pred p;\n\tsetp.ne.u32 p, %4, 0;\n\t"
                 "tcgen05.mma.cta_group::1.kind::tf32 [%0], %1, %2, %3, p;\n\t}"
                 :: "r"(dtmem), "l"(ad), "l"(bd), "r"(IDESC_TF32), "r"(en) : "memory");
}
__device__ __forceinline__ void mbar_wait(unsigned mbar, unsigned parity) {
    asm volatile("{\n\t.reg .pred P1;\n\t"
                 "WL_%=:\n\t"
                 "mbarrier.try_wait.parity.acquire.cta.shared::cta.b64 P1, [%0], %1, 0x989680;\n\t"
                 "@P1 bra.uni WD_%=;\n\t"
                 "bra.uni WL_%=;\n\t"
                 "WD_%=:\n\t}" :: "r"(mbar), "r"(parity) : "memory");
}
#define TCLD32(r, a) \
    asm volatile("tcgen05.ld.sync.aligned.32x32b.x32.b32 " \
        "{%0,%1,%2,%3,%4,%5,%6,%7,%8,%9,%10,%11,%12,%13,%14,%15," \
        "%16,%17,%18,%19,%20,%21,%22,%23,%24,%25,%26,%27,%28,%29,%30,%31}, [%32];" \
        : "=r"((r)[0]),"=r"((r)[1]),"=r"((r)[2]),"=r"((r)[3]),"=r"((r)[4]),"=r"((r)[5]),"=r"((r)[6]),"=r"((r)[7]), \
          "=r"((r)[8]),"=r"((r)[9]),"=r"((r)[10]),"=r"((r)[11]),"=r"((r)[12]),"=r"((r)[13]),"=r"((r)[14]),"=r"((r)[15]), \
          "=r"((r)[16]),"=r"((r)[17]),"=r"((r)[18]),"=r"((r)[19]),"=r"((r)[20]),"=r"((r)[21]),"=r"((r)[22]),"=r"((r)[23]), \
          "=r"((r)[24]),"=r"((r)[25]),"=r"((r)[26]),"=r"((r)[27]),"=r"((r)[28]),"=r"((r)[29]),"=r"((r)[30]),"=r"((r)[31]) \
        : "r"(a))
#endif

__global__ __launch_bounds__(128, 2) void attn_kernel(float* __restrict__ out) {
    const int tid = threadIdx.x;
    const int qt = 15 - ((int)blockIdx.x / 24);   // work-sorted
    const int bh = (int)blockIdx.x % 24;
    const float* hbase = &g_h[(size_t)bh * NSEQ * HD];
    const int q0 = qt * 128;
    const float sc2 = 0.18033688011112042f;       // log2(e)/8

#if HAS_TCGEN05
    extern __shared__ char smem[];
    const unsigned sb = (unsigned)__cvta_generic_to_shared(smem);
    const int wid = tid >> 5;
    const int nkt = 2 * qt + 2;

    if (wid == 0) {
        asm volatile("tcgen05.alloc.cta_group::1.sync.aligned.shared::cta.b32 [%0], %1;"
                     :: "r"(sb + OFF_TMEM), "r"(128u) : "memory");
        asm volatile("tcgen05.relinquish_alloc_permit.cta_group::1.sync.aligned;");
    }
    if (tid == 0) {
        asm volatile("mbarrier.init.shared.b64 [%0], 1;" :: "r"(sb + OFF_MBS) : "memory");
        asm volatile("mbarrier.init.shared.b64 [%0], 1;" :: "r"(sb + OFF_MBO) : "memory");
    }
    __syncthreads();
    unsigned tb;
    asm volatile("ld.shared.b32 %0, [%1];" : "=r"(tb) : "r"(sb + OFF_TMEM));

    // prologue: cp.async Q (SW128, 2 slabs) + K(0)
    #pragma unroll
    for (int i = 0; i < 16; ++i) {
        int idx = tid + i * 128;
        int row = idx >> 4, c = idx & 15;
        unsigned dst = sb + OFF_Q + (c >> 3) * 16384 + sw128(row * 128 + (c & 7) * 16);
        asm volatile("cp.async.cg.shared.global [%0], [%1], 16;"
                     :: "r"(dst), "l"(hbase + (size_t)(q0 + row) * HD + c * 4));
    }
    #pragma unroll
    for (int i = 0; i < 8; ++i) {
        int idx = tid + i * 128;
        int row = idx >> 4, c = idx & 15;
        unsigned dst = sb + OFF_K + (c >> 3) * 8192 + sw128(row * 128 + (c & 7) * 16);
        asm volatile("cp.async.cg.shared.global [%0], [%1], 16;"
                     :: "r"(dst), "l"(hbase + (size_t)row * HD + c * 4));
    }
    asm volatile("cp.async.commit_group;");

    const unsigned long long qdesc  = mk_desc(sb + OFF_Q);
    const unsigned long long kdesc  = mk_desc(sb + OFF_K);
    const unsigned long long ktdesc = mk_desc(sb + OFF_KT);
    const unsigned long long pdesc  = mk_desc(sb + OFF_P);
    float lrow = 0.f;
    int ps = 0, po = 0;

    for (int kt = 0; kt < nkt; ++kt) {
        asm volatile("cp.async.wait_group 0;");
        __syncthreads();
        asm volatile("fence.proxy.async.shared::cta;" ::: "memory");

        // ---- S = Q K^T into TMEM cols 0..63 ----
        if (wid == 0 && elect1()) {
            #pragma unroll
            for (int k8 = 0; k8 < 8; ++k8) {
                unsigned qoff = (k8 >> 2) * 1024 + (k8 & 3) * 2;
                unsigned koff = (k8 >> 2) * 512  + (k8 & 3) * 2;
                mma_tf32_ss(tb, qdesc + qoff, kdesc + koff, k8 > 0);
            }
            asm volatile("tcgen05.commit.cta_group::1.mbarrier::arrive::one.shared::cluster.b64 [%0];"
                         :: "r"(sb + OFF_MBS) : "memory");
        }

        // O(kt-1) must be done before we overwrite KT/P
        if (kt > 0) { mbar_wait(sb + OFF_MBO, po); po ^= 1; }

        // ---- transpose K -> KT (overlaps S mma) ----
        {
            const int td = tid & 63, half = tid >> 6;
            float v[32];
            #pragma unroll
            for (int i = 0; i < 32; ++i) {
                unsigned a = sb + OFF_K + (td >> 5) * 8192
                           + sw128((half * 32 + i) * 128 + (td & 31) * 4);
                asm volatile("ld.shared.b32 %0, [%1];" : "=f"(v[i]) : "r"(a));
            }
            #pragma unroll
            for (int j = 0; j < 8; ++j) {
                unsigned a = sb + OFF_KT + half * 8192 + sw128(td * 128 + j * 16);
                asm volatile("st.shared.v4.b32 [%0], {%1,%2,%3,%4};"
                             :: "r"(a), "f"(v[4*j]), "f"(v[4*j+1]), "f"(v[4*j+2]), "f"(v[4*j+3])
                             : "memory");
            }
        }

        // ---- wait S, read rows, softmax (lane-local; scores provably small) ----
        mbar_wait(sb + OFF_MBS, ps); ps ^= 1;
        asm volatile("tcgen05.fence::after_thread_sync;" ::: "memory");
        unsigned sr[64];
        TCLD32(sr, tb);
        TCLD32(sr + 32, tb + 32);
        asm volatile("tcgen05.wait::ld.sync.aligned;" ::: "memory");
        asm volatile("tcgen05.fence::before_thread_sync;" ::: "memory");

        const int qg = q0 + tid, kbase = kt * 64;
        float p[64], rs = 0.f;
        #pragma unroll
        for (int j = 0; j < 64; ++j) {
            float pj = (kbase + j > qg) ? 0.f : exp2f(__uint_as_float(sr[j]) * sc2);
            p[j] = pj; rs += pj;
        }
        lrow += rs;

        // ---- stage P to SMEM (tf32-rounded, swizzled) ----
        #pragma unroll
        for (int c = 0; c < 16; ++c) {
            unsigned a = sb + OFF_P + (c >> 3) * 16384 + sw128(tid * 128 + (c & 7) * 16);
            asm volatile("st.shared.v4.b32 [%0], {%1,%2,%3,%4};"
                         :: "r"(a), "r"(f2tf(p[4*c])), "r"(f2tf(p[4*c+1])),
                            "r"(f2tf(p[4*c+2])), "r"(f2tf(p[4*c+3])) : "memory");
        }
        __syncthreads();
        asm volatile("fence.proxy.async.shared::cta;" ::: "memory");

        if (kt + 1 < nkt) {
            #pragma unroll
            for (int i = 0; i < 8; ++i) {
                int idx = tid + i * 128;
                int row = idx >> 4, c = idx & 15;
                unsigned dst = sb + OFF_K + (c >> 3) * 8192 + sw128(row * 128 + (c & 7) * 16);
                asm volatile("cp.async.cg.shared.global [%0], [%1], 16;"
                             :: "r"(dst), "l"(hbase + (size_t)((kt + 1) * 64 + row) * HD + c * 4));
            }
            asm volatile("cp.async.commit_group;");
        }

        // ---- O += P·KT into TMEM cols 64..127 ----
        if (wid == 0 && elect1()) {
            #pragma unroll
            for (int k8 = 0; k8 < 8; ++k8) {
                unsigned poff  = (k8 >> 2) * 1024 + (k8 & 3) * 2;
                unsigned ktoff = (k8 >> 2) * 512  + (k8 & 3) * 2;
                mma_tf32_ss(tb + 64, pdesc + poff, ktdesc + ktoff, (kt > 0) || (k8 > 0));
            }
            asm volatile("tcgen05.commit.cta_group::1.mbarrier::arrive::one.shared::cluster.b64 [%0];"
                         :: "r"(sb + OFF_MBO) : "memory");
        }
    }

    // ---- epilogue: read O, normalize, transpose via smem, coalesced store ----
    mbar_wait(sb + OFF_MBO, po);
    asm volatile("tcgen05.fence::after_thread_sync;" ::: "memory");
    unsigned orr[64];
    TCLD32(orr, tb + 64);
    TCLD32(orr + 32, tb + 96);
    asm volatile("tcgen05.wait::ld.sync.aligned;" ::: "memory");
    asm volatile("tcgen05.fence::before_thread_sync;" ::: "memory");
    __syncthreads();

    float* Os = (float*)(smem + 1024);            // 64 x 132 staging (overlays Q/K)
    const float inv = 1.0f / lrow;
    #pragma unroll
    for (int d = 0; d < 64; ++d)
        Os[d * 132 + tid] = __uint_as_float(orr[d]) * inv;
    __syncthreads();
    float* obase = out + (size_t)bh * HD * NSEQ + q0;
    #pragma unroll
    for (int i = 0; i < 16; ++i) {
        int idx = tid + i * 128;
        int d = idx >> 5, q4 = (idx & 31) * 4;
        *(float4*)&obase[(size_t)d * NSEQ + q4] = *(float4*)&Os[d * 132 + q4];
    }
    __syncthreads();
    if (wid == 0)
        asm volatile("tcgen05.dealloc.cta_group::1.sync.aligned.b32 %0, %1;"
                     :: "r"(tb), "r"(128u));
#else
    // -------- scalar fallback (non-103a PTX pass only; correct, slow) --------
    const int qg = q0 + tid;
    const float* hq = hbase + (size_t)qg * HD;
    float o[HD];
    #pragma unroll
    for (int d = 0; d < HD; ++d) o[d] = 0.f;
    float l = 0.f;
    for (int k = 0; k <= qg; ++k) {
        const float* hk = hbase + (size_t)k * HD;
        float s = 0.f;
        #pragma unroll
        for (int d = 0; d < HD; ++d) s += hq[d] * hk[d];
        float pv = exp2f(s * sc2);
        l += pv;
        #pragma unroll
        for (int d = 0; d < HD; ++d) o[d] += pv * hk[d];
    }
    float* obase = out + (size_t)bh * HD * NSEQ + q0;
    float inv = 1.0f / l;
    #pragma unroll
    for (int d = 0; d < HD; ++d)
        obase[(size_t)d * NSEQ + tid] = o[d] * inv;
#endif
}

// ---------------------------------------------------------------------------
extern "C" void kernel_launch(void* const* d_in, const int* in_sizes, int n_in,
                              void* d_out, int out_size) {
    const float* x  = (const float*)d_in[0];
    const float* Wq = (const float*)d_in[1];
    float* out = (float*)d_out;

    const int gemm_smem = 384 * PADG * sizeof(float);
    cudaFuncSetAttribute(qkv_gemm, cudaFuncAttributeMaxDynamicSharedMemorySize, gemm_smem);
    cudaFuncSetAttribute(attn_kernel, cudaFuncAttributeMaxDynamicSharedMemorySize, ATTN_SMEM);

    qkv_gemm<<<dim3(32, 12), 256, gemm_smem>>>(x, Wq);
    attn_kernel<<<384, 128, ATTN_SMEM>>>(out);
}

// round 13
// speedup vs baseline: 2.6333x; 1.3645x over previous
#include <cuda_runtime.h>

#define NH   12
#define HD   64
#define NSEQ 2048
#define NB   2
#define DIN  768

// scratch: h = x @ Wq^T (pre-rounded to tf32), laid out [b][head][q][d]
__device__ float g_h[NB * NH * NSEQ * HD];

__device__ __forceinline__ unsigned f2tf(float f) {
    unsigned u; asm("cvt.rna.tf32.f32 %0, %1;" : "=r"(u) : "f"(f)); return u;
}

// ---------------------------------------------------------------------------
// Arch guard: tcgen05 only exists in the sm_103a-specific compilation pass.
// The non-'a' pass gets correct scalar fallbacks (never selected at runtime).
// ---------------------------------------------------------------------------
#if defined(__CUDA_ARCH_FEAT_SM103_ALL) || defined(__CUDA_ARCH_SPECIFIC__) || !defined(__CUDA_ARCH__)
#define HAS_TCGEN05 1
#else
#define HAS_TCGEN05 0
#endif

#define IDESC_TF32 ((1u<<4) | (2u<<7) | (2u<<10) | (8u<<17) | (8u<<24))  // f32 acc, tf32 a/b, N=64, M=128

#if HAS_TCGEN05
__device__ __forceinline__ unsigned sw128(unsigned b) { return b ^ ((b >> 3) & 0x70); }
__device__ __forceinline__ unsigned long long mk_desc(unsigned addr) {
    return 0x4000404000010000ULL | (unsigned long long)((addr >> 4) & 0x3FFF);
}
__device__ __forceinline__ unsigned elect1() {
    unsigned p;
    asm volatile("{\n\t.reg .pred p;\n\telect.sync _|p, 0xFFFFFFFF;\n\t"
                 "selp.b32 %0, 1, 0, p;\n\t}" : "=r"(p));
    return p;
}
__device__ __forceinline__ void mma_tf32_ss(unsigned dtmem, unsigned long long ad,
                                            unsigned long long bd, unsigned en) {
    asm volatile("{\n\t.reg .pred p;\n\tsetp.ne.u32 p, %4, 0;\n\t"
                 "tcgen05.mma.cta_group::1.kind::tf32 [%0], %1, %2, %3, p;\n\t}"
                 :: "r"(dtmem), "l"(ad), "l"(bd), "r"(IDESC_TF32), "r"(en) : "memory");
}
__device__ __forceinline__ void mbar_wait(unsigned mbar, unsigned parity) {
    asm volatile("{\n\t.reg .pred P1;\n\t"
                 "WL_%=:\n\t"
                 "mbarrier.try_wait.parity.acquire.cta.shared::cta.b64 P1, [%0], %1, 0x989680;\n\t"
                 "@P1 bra.uni WD_%=;\n\t"
                 "bra.uni WL_%=;\n\t"
                 "WD_%=:\n\t}" :: "r"(mbar), "r"(parity) : "memory");
}
__device__ __forceinline__ float ex2(float x) {
    float r; asm("ex2.approx.ftz.f32 %0, %1;" : "=f"(r) : "f"(x)); return r;
}
#define TCLD32(r, a) \
    asm volatile("tcgen05.ld.sync.aligned.32x32b.x32.b32 " \
        "{%0,%1,%2,%3,%4,%5,%6,%7,%8,%9,%10,%11,%12,%13,%14,%15," \
        "%16,%17,%18,%19,%20,%21,%22,%23,%24,%25,%26,%27,%28,%29,%30,%31}, [%32];" \
        : "=r"((r)[0]),"=r"((r)[1]),"=r"((r)[2]),"=r"((r)[3]),"=r"((r)[4]),"=r"((r)[5]),"=r"((r)[6]),"=r"((r)[7]), \
          "=r"((r)[8]),"=r"((r)[9]),"=r"((r)[10]),"=r"((r)[11]),"=r"((r)[12]),"=r"((r)[13]),"=r"((r)[14]),"=r"((r)[15]), \
          "=r"((r)[16]),"=r"((r)[17]),"=r"((r)[18]),"=r"((r)[19]),"=r"((r)[20]),"=r"((r)[21]),"=r"((r)[22]),"=r"((r)[23]), \
          "=r"((r)[24]),"=r"((r)[25]),"=r"((r)[26]),"=r"((r)[27]),"=r"((r)[28]),"=r"((r)[29]),"=r"((r)[30]),"=r"((r)[31]) \
        : "r"(a))
#endif

// ---------------------------------------------------------------------------
// Kernel 1: qkv projection via tcgen05.  D[128 m-rows][64 head-cols] per block.
// cp.async raw fp32, then IN-PLACE tf32-rna rounding pass before MMA issue
// (kind::tf32 truncates mantissas -- biased; rna rounding restores accuracy).
// grid (32, 12), 128 threads, double-buffered chunks of K=64.
// ---------------------------------------------------------------------------
#define GOFF_TMEM 0
#define GOFF_MB   8
#define GOFF_A0   1024
#define GOFF_A1   (GOFF_A0 + 32768)
#define GOFF_B0   (GOFF_A1 + 32768)
#define GOFF_B1   (GOFF_B0 + 16384)
#define GEMM_SMEM (GOFF_B1 + 16384)   // 99328 B

__global__ __launch_bounds__(128, 2) void qkv_gemm(const float* __restrict__ x,
                                                   const float* __restrict__ Wq) {
    const int tid = threadIdx.x;
    const int m0 = blockIdx.x * 128;
    const int head = blockIdx.y;
    const int n0 = head * 64;

#if HAS_TCGEN05
    extern __shared__ char smem[];
    const unsigned sb = (unsigned)__cvta_generic_to_shared(smem);
    const int wid = tid >> 5;

    if (wid == 0) {
        asm volatile("tcgen05.alloc.cta_group::1.sync.aligned.shared::cta.b32 [%0], %1;"
                     :: "r"(sb + GOFF_TMEM), "r"(64u) : "memory");
        asm volatile("tcgen05.relinquish_alloc_permit.cta_group::1.sync.aligned;");
    }
    if (tid == 0)
        asm volatile("mbarrier.init.shared.b64 [%0], 1;" :: "r"(sb + GOFF_MB) : "memory");
    __syncthreads();
    unsigned tb;
    asm volatile("ld.shared.b32 %0, [%1];" : "=r"(tb) : "r"(sb + GOFF_TMEM));

    const unsigned aoffs[2] = {GOFF_A0, GOFF_A1};
    const unsigned boffs[2] = {GOFF_B0, GOFF_B1};

    auto load_chunk = [&](int kk) {
        const int k0 = kk * 64;
        const unsigned ab = sb + aoffs[kk & 1], bb = sb + boffs[kk & 1];
        #pragma unroll
        for (int i = 0; i < 16; ++i) {               // A: 2048 16B chunks
            int idx = tid + i * 128;
            int row = idx >> 4, c = idx & 15;
            unsigned dst = ab + (c >> 3) * 16384 + sw128(row * 128 + (c & 7) * 16);
            asm volatile("cp.async.cg.shared.global [%0], [%1], 16;"
                         :: "r"(dst), "l"(&x[(size_t)(m0 + row) * DIN + k0 + c * 4]));
        }
        #pragma unroll
        for (int i = 0; i < 8; ++i) {                // B: 1024 16B chunks
            int idx = tid + i * 128;
            int row = idx >> 4, c = idx & 15;
            unsigned dst = bb + (c >> 3) * 8192 + sw128(row * 128 + (c & 7) * 16);
            asm volatile("cp.async.cg.shared.global [%0], [%1], 16;"
                         :: "r"(dst), "l"(&Wq[(size_t)(n0 + row) * DIN + k0 + c * 4]));
        }
        asm volatile("cp.async.commit_group;");
    };

    // in-place tf32-rna rounding of one chunk (elementwise; swizzle-agnostic)
    auto round_chunk = [&](int kk) {
        const unsigned ab = sb + aoffs[kk & 1], bb = sb + boffs[kk & 1];
        #pragma unroll
        for (int i = 0; i < 16; ++i) {               // A: 2048 float4s
            unsigned a = ab + (tid + i * 128) * 16;
            float x0, x1, x2, x3;
            asm volatile("ld.shared.v4.b32 {%0,%1,%2,%3}, [%4];"
                         : "=f"(x0), "=f"(x1), "=f"(x2), "=f"(x3) : "r"(a));
            asm volatile("st.shared.v4.b32 [%0], {%1,%2,%3,%4};"
                         :: "r"(a), "r"(f2tf(x0)), "r"(f2tf(x1)),
                            "r"(f2tf(x2)), "r"(f2tf(x3)) : "memory");
        }
        #pragma unroll
        for (int i = 0; i < 8; ++i) {                // B: 1024 float4s
            unsigned a = bb + (tid + i * 128) * 16;
            float x0, x1, x2, x3;
            asm volatile("ld.shared.v4.b32 {%0,%1,%2,%3}, [%4];"
                         : "=f"(x0), "=f"(x1), "=f"(x2), "=f"(x3) : "r"(a));
            asm volatile("st.shared.v4.b32 [%0], {%1,%2,%3,%4};"
                         :: "r"(a), "r"(f2tf(x0)), "r"(f2tf(x1)),
                            "r"(f2tf(x2)), "r"(f2tf(x3)) : "memory");
        }
    };

    load_chunk(0);
    load_chunk(1);

    for (int kk = 0; kk < 12; ++kk) {
        if (kk < 11) asm volatile("cp.async.wait_group 1;");
        else         asm volatile("cp.async.wait_group 0;");
        __syncthreads();

        round_chunk(kk);                             // rna-round before MMA reads
        __syncthreads();
        asm volatile("fence.proxy.async.shared::cta;" ::: "memory");

        if (wid == 0 && elect1()) {
            const unsigned long long ad = mk_desc(sb + aoffs[kk & 1]);
            const unsigned long long bd = mk_desc(sb + boffs[kk & 1]);
            #pragma unroll
            for (int k8 = 0; k8 < 8; ++k8) {
                unsigned ao = (k8 >> 2) * 1024 + (k8 & 3) * 2;
                unsigned bo = (k8 >> 2) * 512  + (k8 & 3) * 2;
                mma_tf32_ss(tb, ad + ao, bd + bo, (kk > 0) || (k8 > 0));
            }
            asm volatile("tcgen05.commit.cta_group::1.mbarrier::arrive::one.shared::cluster.b64 [%0];"
                         :: "r"(sb + GOFF_MB) : "memory");
        }
        // wait EVERY phase in order (parity correctness); frees buffer (kk&1)
        mbar_wait(sb + GOFF_MB, kk & 1);
        if (kk + 2 < 12) load_chunk(kk + 2);
    }

    // epilogue: read D, tf32-round, scatter to g_h[b][head][q][d]
    asm volatile("tcgen05.fence::after_thread_sync;" ::: "memory");
    unsigned dr[64];
    TCLD32(dr, tb);
    TCLD32(dr + 32, tb + 32);
    asm volatile("tcgen05.wait::ld.sync.aligned;" ::: "memory");
    asm volatile("tcgen05.fence::before_thread_sync;" ::: "memory");

    {
        int m = m0 + tid;
        int b = m >> 11, q = m & 2047;
        float* dst = &g_h[((size_t)(b * NH + head) * NSEQ + q) * HD];
        #pragma unroll
        for (int j = 0; j < 16; ++j) {
            float4 v;
            v.x = __uint_as_float(f2tf(__uint_as_float(dr[4*j  ])));
            v.y = __uint_as_float(f2tf(__uint_as_float(dr[4*j+1])));
            v.z = __uint_as_float(f2tf(__uint_as_float(dr[4*j+2])));
            v.w = __uint_as_float(f2tf(__uint_as_float(dr[4*j+3])));
            *(float4*)&dst[4*j] = v;
        }
    }
    __syncthreads();
    if (wid == 0)
        asm volatile("tcgen05.dealloc.cta_group::1.sync.aligned.b32 %0, %1;"
                     :: "r"(tb), "r"(64u));
#else
    // scalar fallback (non-103a pass only; correct, never runs)
    int m = m0 + tid;
    int b = m >> 11, q = m & 2047;
    float* dst = &g_h[((size_t)(b * NH + head) * NSEQ + q) * HD];
    for (int c = 0; c < 64; ++c) {
        float s = 0.f;
        for (int k = 0; k < DIN; ++k)
            s += x[(size_t)m * DIN + k] * Wq[(size_t)(n0 + c) * DIN + k];
        unsigned u = f2tf(s);
        dst[c] = __uint_as_float(u);
    }
#endif
}

// ---------------------------------------------------------------------------
// Kernel 2: tcgen05 causal flash attention (unchanged from R12 -- inputs from
// g_h are tf32-exact, so kind::tf32 truncation is a no-op here).
// ---------------------------------------------------------------------------
#define OFF_TMEM 0
#define OFF_MBS  8
#define OFF_MBO  16
#define OFF_Q    1024
#define OFF_K    (OFF_Q  + 32768)
#define OFF_KT   (OFF_K  + 16384)
#define OFF_P    (OFF_KT + 16384)
#define ATTN_SMEM (OFF_P + 32768)    // 99328 B

__global__ __launch_bounds__(128, 2) void attn_kernel(float* __restrict__ out) {
    const int tid = threadIdx.x;
    const int qt = 15 - ((int)blockIdx.x / 24);   // work-sorted
    const int bh = (int)blockIdx.x % 24;
    const float* hbase = &g_h[(size_t)bh * NSEQ * HD];
    const int q0 = qt * 128;
    const float sc2 = 0.18033688011112042f;       // log2(e)/8

#if HAS_TCGEN05
    extern __shared__ char smem[];
    const unsigned sb = (unsigned)__cvta_generic_to_shared(smem);
    const int wid = tid >> 5;
    const int nkt = 2 * qt + 2;

    if (wid == 0) {
        asm volatile("tcgen05.alloc.cta_group::1.sync.aligned.shared::cta.b32 [%0], %1;"
                     :: "r"(sb + OFF_TMEM), "r"(128u) : "memory");
        asm volatile("tcgen05.relinquish_alloc_permit.cta_group::1.sync.aligned;");
    }
    if (tid == 0) {
        asm volatile("mbarrier.init.shared.b64 [%0], 1;" :: "r"(sb + OFF_MBS) : "memory");
        asm volatile("mbarrier.init.shared.b64 [%0], 1;" :: "r"(sb + OFF_MBO) : "memory");
    }
    __syncthreads();
    unsigned tb;
    asm volatile("ld.shared.b32 %0, [%1];" : "=r"(tb) : "r"(sb + OFF_TMEM));

    #pragma unroll
    for (int i = 0; i < 16; ++i) {
        int idx = tid + i * 128;
        int row = idx >> 4, c = idx & 15;
        unsigned dst = sb + OFF_Q + (c >> 3) * 16384 + sw128(row * 128 + (c & 7) * 16);
        asm volatile("cp.async.cg.shared.global [%0], [%1], 16;"
                     :: "r"(dst), "l"(hbase + (size_t)(q0 + row) * HD + c * 4));
    }
    #pragma unroll
    for (int i = 0; i < 8; ++i) {
        int idx = tid + i * 128;
        int row = idx >> 4, c = idx & 15;
        unsigned dst = sb + OFF_K + (c >> 3) * 8192 + sw128(row * 128 + (c & 7) * 16);
        asm volatile("cp.async.cg.shared.global [%0], [%1], 16;"
                     :: "r"(dst), "l"(hbase + (size_t)row * HD + c * 4));
    }
    asm volatile("cp.async.commit_group;");

    const unsigned long long qdesc  = mk_desc(sb + OFF_Q);
    const unsigned long long kdesc  = mk_desc(sb + OFF_K);
    const unsigned long long ktdesc = mk_desc(sb + OFF_KT);
    const unsigned long long pdesc  = mk_desc(sb + OFF_P);
    float lrow = 0.f;
    int ps = 0, po = 0;

    for (int kt = 0; kt < nkt; ++kt) {
        asm volatile("cp.async.wait_group 0;");
        __syncthreads();
        asm volatile("fence.proxy.async.shared::cta;" ::: "memory");

        // ---- S = Q K^T into TMEM cols 0..63 ----
        if (wid == 0 && elect1()) {
            #pragma unroll
            for (int k8 = 0; k8 < 8; ++k8) {
                unsigned qoff = (k8 >> 2) * 1024 + (k8 & 3) * 2;
                unsigned koff = (k8 >> 2) * 512  + (k8 & 3) * 2;
                mma_tf32_ss(tb, qdesc + qoff, kdesc + koff, k8 > 0);
            }
            asm volatile("tcgen05.commit.cta_group::1.mbarrier::arrive::one.shared::cluster.b64 [%0];"
                         :: "r"(sb + OFF_MBS) : "memory");
        }

        if (kt > 0) { mbar_wait(sb + OFF_MBO, po); po ^= 1; }

        // ---- transpose K -> KT (overlaps S mma) ----
        {
            const int td = tid & 63, half = tid >> 6;
            float v[32];
            #pragma unroll
            for (int i = 0; i < 32; ++i) {
                unsigned a = sb + OFF_K + (td >> 5) * 8192
                           + sw128((half * 32 + i) * 128 + (td & 31) * 4);
                asm volatile("ld.shared.b32 %0, [%1];" : "=f"(v[i]) : "r"(a));
            }
            #pragma unroll
            for (int j = 0; j < 8; ++j) {
                unsigned a = sb + OFF_KT + half * 8192 + sw128(td * 128 + j * 16);
                asm volatile("st.shared.v4.b32 [%0], {%1,%2,%3,%4};"
                             :: "r"(a), "f"(v[4*j]), "f"(v[4*j+1]), "f"(v[4*j+2]), "f"(v[4*j+3])
                             : "memory");
            }
        }

        // ---- wait S, softmax (lane-local; mask only on diagonal tiles) ----
        mbar_wait(sb + OFF_MBS, ps); ps ^= 1;
        asm volatile("tcgen05.fence::after_thread_sync;" ::: "memory");
        unsigned sr[64];
        TCLD32(sr, tb);
        TCLD32(sr + 32, tb + 32);
        asm volatile("tcgen05.wait::ld.sync.aligned;" ::: "memory");
        asm volatile("tcgen05.fence::before_thread_sync;" ::: "memory");

        const int qg = q0 + tid, kbase = kt * 64;
        float p[64], rs = 0.f;
        if (kbase + 63 <= qg) {
            #pragma unroll
            for (int j = 0; j < 64; ++j) {
                float pj = ex2(__uint_as_float(sr[j]) * sc2);
                p[j] = pj; rs += pj;
            }
        } else {
            #pragma unroll
            for (int j = 0; j < 64; ++j) {
                float pj = (kbase + j > qg) ? 0.f : ex2(__uint_as_float(sr[j]) * sc2);
                p[j] = pj; rs += pj;
            }
        }
        lrow += rs;

        // ---- stage P to SMEM (tf32-rounded, swizzled) ----
        #pragma unroll
        for (int c = 0; c < 16; ++c) {
            unsigned a = sb + OFF_P + (c >> 3) * 16384 + sw128(tid * 128 + (c & 7) * 16);
            asm volatile("st.shared.v4.b32 [%0], {%1,%2,%3,%4};"
                         :: "r"(a), "r"(f2tf(p[4*c])), "r"(f2tf(p[4*c+1])),
                            "r"(f2tf(p[4*c+2])), "r"(f2tf(p[4*c+3])) : "memory");
        }
        __syncthreads();
        asm volatile("fence.proxy.async.shared::cta;" ::: "memory");

        if (kt + 1 < nkt) {
            #pragma unroll
            for (int i = 0; i < 8; ++i) {
                int idx = tid + i * 128;
                int row = idx >> 4, c = idx & 15;
                unsigned dst = sb + OFF_K + (c >> 3) * 8192 + sw128(row * 128 + (c & 7) * 16);
                asm volatile("cp.async.cg.shared.global [%0], [%1], 16;"
                             :: "r"(dst), "l"(hbase + (size_t)((kt + 1) * 64 + row) * HD + c * 4));
            }
            asm volatile("cp.async.commit_group;");
        }

        // ---- O += P·KT into TMEM cols 64..127 ----
        if (wid == 0 && elect1()) {
            #pragma unroll
            for (int k8 = 0; k8 < 8; ++k8) {
                unsigned poff  = (k8 >> 2) * 1024 + (k8 & 3) * 2;
                unsigned ktoff = (k8 >> 2) * 512  + (k8 & 3) * 2;
                mma_tf32_ss(tb + 64, pdesc + poff, ktdesc + ktoff, (kt > 0) || (k8 > 0));
            }
            asm volatile("tcgen05.commit.cta_group::1.mbarrier::arrive::one.shared::cluster.b64 [%0];"
                         :: "r"(sb + OFF_MBO) : "memory");
        }
    }

    // ---- epilogue ----
    mbar_wait(sb + OFF_MBO, po);
    asm volatile("tcgen05.fence::after_thread_sync;" ::: "memory");
    unsigned orr[64];
    TCLD32(orr, tb + 64);
    TCLD32(orr + 32, tb + 96);
    asm volatile("tcgen05.wait::ld.sync.aligned;" ::: "memory");
    asm volatile("tcgen05.fence::before_thread_sync;" ::: "memory");
    __syncthreads();

    float* Os = (float*)(smem + 1024);            // 64 x 132 staging (overlays Q/K)
    const float inv = 1.0f / lrow;
    #pragma unroll
    for (int d = 0; d < 64; ++d)
        Os[d * 132 + tid] = __uint_as_float(orr[d]) * inv;
    __syncthreads();
    float* obase = out + (size_t)bh * HD * NSEQ + q0;
    #pragma unroll
    for (int i = 0; i < 16; ++i) {
        int idx = tid + i * 128;
        int d = idx >> 5, q4 = (idx & 31) * 4;
        *(float4*)&obase[(size_t)d * NSEQ + q4] = *(float4*)&Os[d * 132 + q4];
    }
    __syncthreads();
    if (wid == 0)
        asm volatile("tcgen05.dealloc.cta_group::1.sync.aligned.b32 %0, %1;"
                     :: "r"(tb), "r"(128u));
#else
    // scalar fallback (non-103a pass only; correct, never runs)
    const int qg = q0 + tid;
    const float* hq = hbase + (size_t)qg * HD;
    float o[HD];
    #pragma unroll
    for (int d = 0; d < HD; ++d) o[d] = 0.f;
    float l = 0.f;
    for (int k = 0; k <= qg; ++k) {
        const float* hk = hbase + (size_t)k * HD;
        float s = 0.f;
        #pragma unroll
        for (int d = 0; d < HD; ++d) s += hq[d] * hk[d];
        float pv = exp2f(s * sc2);
        l += pv;
        #pragma unroll
        for (int d = 0; d < HD; ++d) o[d] += pv * hk[d];
    }
    float* obase = out + (size_t)bh * HD * NSEQ + q0;
    float inv = 1.0f / l;
    #pragma unroll
    for (int d = 0; d < HD; ++d)
        obase[(size_t)d * NSEQ + tid] = o[d] * inv;
#endif
}

// ---------------------------------------------------------------------------
extern "C" void kernel_launch(void* const* d_in, const int* in_sizes, int n_in,
                              void* d_out, int out_size) {
    const float* x  = (const float*)d_in[0];
    const float* Wq = (const float*)d_in[1];
    float* out = (float*)d_out;

    cudaFuncSetAttribute(qkv_gemm, cudaFuncAttributeMaxDynamicSharedMemorySize, GEMM_SMEM);
    cudaFuncSetAttribute(attn_kernel, cudaFuncAttributeMaxDynamicSharedMemorySize, ATTN_SMEM);

    qkv_gemm<<<dim3(32, 12), 128, GEMM_SMEM>>>(x, Wq);
    attn_kernel<<<384, 128, ATTN_SMEM>>>(out);
}

// round 14
// speedup vs baseline: 2.8239x; 1.0723x over previous
#include <cuda_runtime.h>

#define NH   12
#define HD   64
#define NSEQ 2048
#define NB   2
#define DIN  768

// scratch: h = x @ Wq^T (tf32-exact), laid out [b][head][q][d]
__device__ float g_h[NB * NH * NSEQ * HD];
// tf32-rna pre-rounded copies of the inputs
__device__ float g_x[NB * NSEQ * DIN];
__device__ float g_w[DIN * DIN];

__device__ __forceinline__ unsigned f2tf(float f) {
    unsigned u; asm("cvt.rna.tf32.f32 %0, %1;" : "=r"(u) : "f"(f)); return u;
}

// ---------------------------------------------------------------------------
// Arch guard: tcgen05 only exists in the sm_103a-specific compilation pass.
// ---------------------------------------------------------------------------
#if defined(__CUDA_ARCH_FEAT_SM103_ALL) || defined(__CUDA_ARCH_SPECIFIC__) || !defined(__CUDA_ARCH__)
#define HAS_TCGEN05 1
#else
#define HAS_TCGEN05 0
#endif

#define IDESC_TF32 ((1u<<4) | (2u<<7) | (2u<<10) | (8u<<17) | (8u<<24))  // f32 acc, tf32 a/b, N=64, M=128

#if HAS_TCGEN05
__device__ __forceinline__ unsigned sw128(unsigned b) { return b ^ ((b >> 3) & 0x70); }
__device__ __forceinline__ unsigned long long mk_desc(unsigned addr) {
    return 0x4000404000010000ULL | (unsigned long long)((addr >> 4) & 0x3FFF);
}
__device__ __forceinline__ unsigned elect1() {
    unsigned p;
    asm volatile("{\n\t.reg .pred p;\n\telect.sync _|p, 0xFFFFFFFF;\n\t"
                 "selp.b32 %0, 1, 0, p;\n\t}" : "=r"(p));
    return p;
}
__device__ __forceinline__ void mma_tf32_ss(unsigned dtmem, unsigned long long ad,
                                            unsigned long long bd, unsigned en) {
    asm volatile("{\n\t.reg .pred p;\n\tsetp.ne.u32 p, %4, 0;\n\t"
                 "tcgen05.mma.cta_group::1.kind::tf32 [%0], %1, %2, %3, p;\n\t}"
                 :: "r"(dtmem), "l"(ad), "l"(bd), "r"(IDESC_TF32), "r"(en) : "memory");
}
__device__ __forceinline__ void mbar_wait(unsigned mbar, unsigned parity) {
    asm volatile("{\n\t.reg .pred P1;\n\t"
                 "WL_%=:\n\t"
                 "mbarrier.try_wait.parity.acquire.cta.shared::cta.b64 P1, [%0], %1, 0x989680;\n\t"
                 "@P1 bra.uni WD_%=;\n\t"
                 "bra.uni WL_%=;\n\t"
                 "WD_%=:\n\t}" :: "r"(mbar), "r"(parity) : "memory");
}
__device__ __forceinline__ float ex2(float x) {
    float r; asm("ex2.approx.ftz.f32 %0, %1;" : "=f"(r) : "f"(x)); return r;
}
#define TCLD32(r, a) \
    asm volatile("tcgen05.ld.sync.aligned.32x32b.x32.b32 " \
        "{%0,%1,%2,%3,%4,%5,%6,%7,%8,%9,%10,%11,%12,%13,%14,%15," \
        "%16,%17,%18,%19,%20,%21,%22,%23,%24,%25,%26,%27,%28,%29,%30,%31}, [%32];" \
        : "=r"((r)[0]),"=r"((r)[1]),"=r"((r)[2]),"=r"((r)[3]),"=r"((r)[4]),"=r"((r)[5]),"=r"((r)[6]),"=r"((r)[7]), \
          "=r"((r)[8]),"=r"((r)[9]),"=r"((r)[10]),"=r"((r)[11]),"=r"((r)[12]),"=r"((r)[13]),"=r"((r)[14]),"=r"((r)[15]), \
          "=r"((r)[16]),"=r"((r)[17]),"=r"((r)[18]),"=r"((r)[19]),"=r"((r)[20]),"=r"((r)[21]),"=r"((r)[22]),"=r"((r)[23]), \
          "=r"((r)[24]),"=r"((r)[25]),"=r"((r)[26]),"=r"((r)[27]),"=r"((r)[28]),"=r"((r)[29]),"=r"((r)[30]),"=r"((r)[31]) \
        : "r"(a))
#endif

// ---------------------------------------------------------------------------
// Kernel 0: one-shot tf32-rna rounding of inputs into g_x / g_w.
// 933888 float4s total (x: 786432, Wq: 147456); grid 3648 x 256 exact.
// ---------------------------------------------------------------------------
__global__ __launch_bounds__(256) void round_inputs(const float* __restrict__ x,
                                                    const float* __restrict__ Wq) {
    int i = blockIdx.x * 256 + threadIdx.x;
    if (i < 786432) {
        float4 v = ((const float4*)x)[i];
        float4 r;
        r.x = __uint_as_float(f2tf(v.x)); r.y = __uint_as_float(f2tf(v.y));
        r.z = __uint_as_float(f2tf(v.z)); r.w = __uint_as_float(f2tf(v.w));
        ((float4*)g_x)[i] = r;
    } else {
        int j = i - 786432;
        float4 v = ((const float4*)Wq)[j];
        float4 r;
        r.x = __uint_as_float(f2tf(v.x)); r.y = __uint_as_float(f2tf(v.y));
        r.z = __uint_as_float(f2tf(v.z)); r.w = __uint_as_float(f2tf(v.w));
        ((float4*)g_w)[j] = r;
    }
}

// ---------------------------------------------------------------------------
// Kernel 1: qkv projection via tcgen05 on pre-rounded g_x/g_w (tf32-exact,
// so kind::tf32 mantissa truncation is a no-op). Double-buffered K=64 chunks.
// grid (32, 12), 128 threads.
// ---------------------------------------------------------------------------
#define GOFF_TMEM 0
#define GOFF_MB   8
#define GOFF_A0   1024
#define GOFF_A1   (GOFF_A0 + 32768)
#define GOFF_B0   (GOFF_A1 + 32768)
#define GOFF_B1   (GOFF_B0 + 16384)
#define GEMM_SMEM (GOFF_B1 + 16384)   // 99328 B

__global__ __launch_bounds__(128, 2) void qkv_gemm() {
    const int tid = threadIdx.x;
    const int m0 = blockIdx.x * 128;
    const int head = blockIdx.y;
    const int n0 = head * 64;

#if HAS_TCGEN05
    extern __shared__ char smem[];
    const unsigned sb = (unsigned)__cvta_generic_to_shared(smem);
    const int wid = tid >> 5;

    if (wid == 0) {
        asm volatile("tcgen05.alloc.cta_group::1.sync.aligned.shared::cta.b32 [%0], %1;"
                     :: "r"(sb + GOFF_TMEM), "r"(64u) : "memory");
        asm volatile("tcgen05.relinquish_alloc_permit.cta_group::1.sync.aligned;");
    }
    if (tid == 0)
        asm volatile("mbarrier.init.shared.b64 [%0], 1;" :: "r"(sb + GOFF_MB) : "memory");
    __syncthreads();
    unsigned tb;
    asm volatile("ld.shared.b32 %0, [%1];" : "=r"(tb) : "r"(sb + GOFF_TMEM));

    const unsigned aoffs[2] = {GOFF_A0, GOFF_A1};
    const unsigned boffs[2] = {GOFF_B0, GOFF_B1};

    auto load_chunk = [&](int kk) {
        const int k0 = kk * 64;
        const unsigned ab = sb + aoffs[kk & 1], bb = sb + boffs[kk & 1];
        #pragma unroll
        for (int i = 0; i < 16; ++i) {               // A: 2048 16B chunks
            int idx = tid + i * 128;
            int row = idx >> 4, c = idx & 15;
            unsigned dst = ab + (c >> 3) * 16384 + sw128(row * 128 + (c & 7) * 16);
            asm volatile("cp.async.cg.shared.global [%0], [%1], 16;"
                         :: "r"(dst), "l"(&g_x[(size_t)(m0 + row) * DIN + k0 + c * 4]));
        }
        #pragma unroll
        for (int i = 0; i < 8; ++i) {                // B: 1024 16B chunks
            int idx = tid + i * 128;
            int row = idx >> 4, c = idx & 15;
            unsigned dst = bb + (c >> 3) * 8192 + sw128(row * 128 + (c & 7) * 16);
            asm volatile("cp.async.cg.shared.global [%0], [%1], 16;"
                         :: "r"(dst), "l"(&g_w[(size_t)(n0 + row) * DIN + k0 + c * 4]));
        }
        asm volatile("cp.async.commit_group;");
    };

    load_chunk(0);
    load_chunk(1);

    for (int kk = 0; kk < 12; ++kk) {
        if (kk < 11) asm volatile("cp.async.wait_group 1;");
        else         asm volatile("cp.async.wait_group 0;");
        __syncthreads();
        asm volatile("fence.proxy.async.shared::cta;" ::: "memory");

        if (wid == 0 && elect1()) {
            const unsigned long long ad = mk_desc(sb + aoffs[kk & 1]);
            const unsigned long long bd = mk_desc(sb + boffs[kk & 1]);
            #pragma unroll
            for (int k8 = 0; k8 < 8; ++k8) {
                unsigned ao = (k8 >> 2) * 1024 + (k8 & 3) * 2;
                unsigned bo = (k8 >> 2) * 512  + (k8 & 3) * 2;
                mma_tf32_ss(tb, ad + ao, bd + bo, (kk > 0) || (k8 > 0));
            }
            asm volatile("tcgen05.commit.cta_group::1.mbarrier::arrive::one.shared::cluster.b64 [%0];"
                         :: "r"(sb + GOFF_MB) : "memory");
        }
        // wait EVERY phase in order (parity correctness); frees buffer (kk&1)
        mbar_wait(sb + GOFF_MB, kk & 1);
        if (kk + 2 < 12) load_chunk(kk + 2);
    }

    // epilogue: read D, tf32-round, scatter to g_h[b][head][q][d]
    asm volatile("tcgen05.fence::after_thread_sync;" ::: "memory");
    unsigned dr[64];
    TCLD32(dr, tb);
    TCLD32(dr + 32, tb + 32);
    asm volatile("tcgen05.wait::ld.sync.aligned;" ::: "memory");
    asm volatile("tcgen05.fence::before_thread_sync;" ::: "memory");

    {
        int m = m0 + tid;
        int b = m >> 11, q = m & 2047;
        float* dst = &g_h[((size_t)(b * NH + head) * NSEQ + q) * HD];
        #pragma unroll
        for (int j = 0; j < 16; ++j) {
            float4 v;
            v.x = __uint_as_float(f2tf(__uint_as_float(dr[4*j  ])));
            v.y = __uint_as_float(f2tf(__uint_as_float(dr[4*j+1])));
            v.z = __uint_as_float(f2tf(__uint_as_float(dr[4*j+2])));
            v.w = __uint_as_float(f2tf(__uint_as_float(dr[4*j+3])));
            *(float4*)&dst[4*j] = v;
        }
    }
    __syncthreads();
    if (wid == 0)
        asm volatile("tcgen05.dealloc.cta_group::1.sync.aligned.b32 %0, %1;"
                     :: "r"(tb), "r"(64u));
#else
    // scalar fallback (non-103a pass only; correct, never runs)
    int m = m0 + tid;
    int b = m >> 11, q = m & 2047;
    float* dst = &g_h[((size_t)(b * NH + head) * NSEQ + q) * HD];
    for (int c = 0; c < 64; ++c) {
        float s = 0.f;
        for (int k = 0; k < DIN; ++k)
            s += g_x[(size_t)m * DIN + k] * g_w[(size_t)(n0 + c) * DIN + k];
        dst[c] = __uint_as_float(f2tf(s));
    }
#endif
}

// ---------------------------------------------------------------------------
// Kernel 2: tcgen05 causal flash attention. K prefetch hoisted to right after
// mbar_wait(S) + syncthreads so the load hides behind softmax + P + O-mma.
// ---------------------------------------------------------------------------
#define OFF_TMEM 0
#define OFF_MBS  8
#define OFF_MBO  16
#define OFF_Q    1024
#define OFF_K    (OFF_Q  + 32768)
#define OFF_KT   (OFF_K  + 16384)
#define OFF_P    (OFF_KT + 16384)
#define ATTN_SMEM (OFF_P + 32768)    // 99328 B

__global__ __launch_bounds__(128, 2) void attn_kernel(float* __restrict__ out) {
    const int tid = threadIdx.x;
    const int qt = 15 - ((int)blockIdx.x / 24);   // work-sorted
    const int bh = (int)blockIdx.x % 24;
    const float* hbase = &g_h[(size_t)bh * NSEQ * HD];
    const int q0 = qt * 128;
    const float sc2 = 0.18033688011112042f;       // log2(e)/8

#if HAS_TCGEN05
    extern __shared__ char smem[];
    const unsigned sb = (unsigned)__cvta_generic_to_shared(smem);
    const int wid = tid >> 5;
    const int nkt = 2 * qt + 2;

    if (wid == 0) {
        asm volatile("tcgen05.alloc.cta_group::1.sync.aligned.shared::cta.b32 [%0], %1;"
                     :: "r"(sb + OFF_TMEM), "r"(128u) : "memory");
        asm volatile("tcgen05.relinquish_alloc_permit.cta_group::1.sync.aligned;");
    }
    if (tid == 0) {
        asm volatile("mbarrier.init.shared.b64 [%0], 1;" :: "r"(sb + OFF_MBS) : "memory");
        asm volatile("mbarrier.init.shared.b64 [%0], 1;" :: "r"(sb + OFF_MBO) : "memory");
    }
    __syncthreads();
    unsigned tb;
    asm volatile("ld.shared.b32 %0, [%1];" : "=r"(tb) : "r"(sb + OFF_TMEM));

    #pragma unroll
    for (int i = 0; i < 16; ++i) {
        int idx = tid + i * 128;
        int row = idx >> 4, c = idx & 15;
        unsigned dst = sb + OFF_Q + (c >> 3) * 16384 + sw128(row * 128 + (c & 7) * 16);
        asm volatile("cp.async.cg.shared.global [%0], [%1], 16;"
                     :: "r"(dst), "l"(hbase + (size_t)(q0 + row) * HD + c * 4));
    }
    #pragma unroll
    for (int i = 0; i < 8; ++i) {
        int idx = tid + i * 128;
        int row = idx >> 4, c = idx & 15;
        unsigned dst = sb + OFF_K + (c >> 3) * 8192 + sw128(row * 128 + (c & 7) * 16);
        asm volatile("cp.async.cg.shared.global [%0], [%1], 16;"
                     :: "r"(dst), "l"(hbase + (size_t)row * HD + c * 4));
    }
    asm volatile("cp.async.commit_group;");

    const unsigned long long qdesc  = mk_desc(sb + OFF_Q);
    const unsigned long long kdesc  = mk_desc(sb + OFF_K);
    const unsigned long long ktdesc = mk_desc(sb + OFF_KT);
    const unsigned long long pdesc  = mk_desc(sb + OFF_P);
    float lrow = 0.f;
    int ps = 0, po = 0;

    for (int kt = 0; kt < nkt; ++kt) {
        asm volatile("cp.async.wait_group 0;");
        __syncthreads();
        asm volatile("fence.proxy.async.shared::cta;" ::: "memory");

        // ---- S = Q K^T into TMEM cols 0..63 ----
        if (wid == 0 && elect1()) {
            #pragma unroll
            for (int k8 = 0; k8 < 8; ++k8) {
                unsigned qoff = (k8 >> 2) * 1024 + (k8 & 3) * 2;
                unsigned koff = (k8 >> 2) * 512  + (k8 & 3) * 2;
                mma_tf32_ss(tb, qdesc + qoff, kdesc + koff, k8 > 0);
            }
            asm volatile("tcgen05.commit.cta_group::1.mbarrier::arrive::one.shared::cluster.b64 [%0];"
                         :: "r"(sb + OFF_MBS) : "memory");
        }

        if (kt > 0) { mbar_wait(sb + OFF_MBO, po); po ^= 1; }

        // ---- transpose K -> KT (overlaps S mma) ----
        {
            const int td = tid & 63, half = tid >> 6;
            float v[32];
            #pragma unroll
            for (int i = 0; i < 32; ++i) {
                unsigned a = sb + OFF_K + (td >> 5) * 8192
                           + sw128((half * 32 + i) * 128 + (td & 31) * 4);
                asm volatile("ld.shared.b32 %0, [%1];" : "=f"(v[i]) : "r"(a));
            }
            #pragma unroll
            for (int j = 0; j < 8; ++j) {
                unsigned a = sb + OFF_KT + half * 8192 + sw128(td * 128 + j * 16);
                asm volatile("st.shared.v4.b32 [%0], {%1,%2,%3,%4};"
                             :: "r"(a), "f"(v[4*j]), "f"(v[4*j+1]), "f"(v[4*j+2]), "f"(v[4*j+3])
                             : "memory");
            }
        }

        // ---- S done (tensor finished reading Ks) + all transpose reads done
        //      -> prefetch K(kt+1) NOW so it hides behind softmax+P+O ----
        mbar_wait(sb + OFF_MBS, ps); ps ^= 1;
        __syncthreads();                     // transpose reads of Ks complete everywhere
        if (kt + 1 < nkt) {
            #pragma unroll
            for (int i = 0; i < 8; ++i) {
                int idx = tid + i * 128;
                int row = idx >> 4, c = idx & 15;
                unsigned dst = sb + OFF_K + (c >> 3) * 8192 + sw128(row * 128 + (c & 7) * 16);
                asm volatile("cp.async.cg.shared.global [%0], [%1], 16;"
                             :: "r"(dst), "l"(hbase + (size_t)((kt + 1) * 64 + row) * HD + c * 4));
            }
            asm volatile("cp.async.commit_group;");
        }

        // ---- read S rows, softmax (lane-local; mask only diagonal tiles) ----
        asm volatile("tcgen05.fence::after_thread_sync;" ::: "memory");
        unsigned sr[64];
        TCLD32(sr, tb);
        TCLD32(sr + 32, tb + 32);
        asm volatile("tcgen05.wait::ld.sync.aligned;" ::: "memory");
        asm volatile("tcgen05.fence::before_thread_sync;" ::: "memory");

        const int qg = q0 + tid, kbase = kt * 64;
        float p[64], rs = 0.f;
        if (kbase + 63 <= qg) {
            #pragma unroll
            for (int j = 0; j < 64; ++j) {
                float pj = ex2(__uint_as_float(sr[j]) * sc2);
                p[j] = pj; rs += pj;
            }
        } else {
            #pragma unroll
            for (int j = 0; j < 64; ++j) {
                float pj = (kbase + j > qg) ? 0.f : ex2(__uint_as_float(sr[j]) * sc2);
                p[j] = pj; rs += pj;
            }
        }
        lrow += rs;

        // ---- stage P to SMEM (tf32-rounded, swizzled) ----
        #pragma unroll
        for (int c = 0; c < 16; ++c) {
            unsigned a = sb + OFF_P + (c >> 3) * 16384 + sw128(tid * 128 + (c & 7) * 16);
            asm volatile("st.shared.v4.b32 [%0], {%1,%2,%3,%4};"
                         :: "r"(a), "r"(f2tf(p[4*c])), "r"(f2tf(p[4*c+1])),
                            "r"(f2tf(p[4*c+2])), "r"(f2tf(p[4*c+3])) : "memory");
        }
        __syncthreads();                     // P + KT visible to all
        asm volatile("fence.proxy.async.shared::cta;" ::: "memory");

        // ---- O += P·KT into TMEM cols 64..127 ----
        if (wid == 0 && elect1()) {
            #pragma unroll
            for (int k8 = 0; k8 < 8; ++k8) {
                unsigned poff  = (k8 >> 2) * 1024 + (k8 & 3) * 2;
                unsigned ktoff = (k8 >> 2) * 512  + (k8 & 3) * 2;
                mma_tf32_ss(tb + 64, pdesc + poff, ktdesc + ktoff, (kt > 0) || (k8 > 0));
            }
            asm volatile("tcgen05.commit.cta_group::1.mbarrier::arrive::one.shared::cluster.b64 [%0];"
                         :: "r"(sb + OFF_MBO) : "memory");
        }
    }

    // ---- epilogue ----
    mbar_wait(sb + OFF_MBO, po);
    asm volatile("tcgen05.fence::after_thread_sync;" ::: "memory");
    unsigned orr[64];
    TCLD32(orr, tb + 64);
    TCLD32(orr + 32, tb + 96);
    asm volatile("tcgen05.wait::ld.sync.aligned;" ::: "memory");
    asm volatile("tcgen05.fence::before_thread_sync;" ::: "memory");
    __syncthreads();

    float* Os = (float*)(smem + 1024);            // 64 x 132 staging (overlays Q/K)
    const float inv = 1.0f / lrow;
    #pragma unroll
    for (int d = 0; d < 64; ++d)
        Os[d * 132 + tid] = __uint_as_float(orr[d]) * inv;
    __syncthreads();
    float* obase = out + (size_t)bh * HD * NSEQ + q0;
    #pragma unroll
    for (int i = 0; i < 16; ++i) {
        int idx = tid + i * 128;
        int d = idx >> 5, q4 = (idx & 31) * 4;
        *(float4*)&obase[(size_t)d * NSEQ + q4] = *(float4*)&Os[d * 132 + q4];
    }
    __syncthreads();
    if (wid == 0)
        asm volatile("tcgen05.dealloc.cta_group::1.sync.aligned.b32 %0, %1;"
                     :: "r"(tb), "r"(128u));
#else
    // scalar fallback (non-103a pass only; correct, never runs)
    const int qg = q0 + tid;
    const float* hq = hbase + (size_t)qg * HD;
    float o[HD];
    #pragma unroll
    for (int d = 0; d < HD; ++d) o[d] = 0.f;
    float l = 0.f;
    for (int k = 0; k <= qg; ++k) {
        const float* hk = hbase + (size_t)k * HD;
        float s = 0.f;
        #pragma unroll
        for (int d = 0; d < HD; ++d) s += hq[d] * hk[d];
        float pv = exp2f(s * sc2);
        l += pv;
        #pragma unroll
        for (int d = 0; d < HD; ++d) o[d] += pv * hk[d];
    }
    float* obase = out + (size_t)bh * HD * NSEQ + q0;
    float inv = 1.0f / l;
    #pragma unroll
    for (int d = 0; d < HD; ++d)
        obase[(size_t)d * NSEQ + tid] = o[d] * inv;
#endif
}

// ---------------------------------------------------------------------------
extern "C" void kernel_launch(void* const* d_in, const int* in_sizes, int n_in,
                              void* d_out, int out_size) {
    const float* x  = (const float*)d_in[0];
    const float* Wq = (const float*)d_in[1];
    float* out = (float*)d_out;

    cudaFuncSetAttribute(qkv_gemm, cudaFuncAttributeMaxDynamicSharedMemorySize, GEMM_SMEM);
    cudaFuncSetAttribute(attn_kernel, cudaFuncAttributeMaxDynamicSharedMemorySize, ATTN_SMEM);

    round_inputs<<<3648, 256>>>(x, Wq);
    qkv_gemm<<<dim3(32, 12), 128, GEMM_SMEM>>>();
    attn_kernel<<<384, 128, ATTN_SMEM>>>(out);
}

// round 16
// speedup vs baseline: 2.8378x; 1.0049x over previous
#include <cuda_runtime.h>

#define NH   12
#define HD   64
#define NSEQ 2048
#define NB   2
#define DIN  768

// scratch: h = x @ Wq^T (tf32-exact), laid out [b][head][q][d]
__device__ float g_h[NB * NH * NSEQ * HD];
// tf32-rna pre-rounded copies of the inputs
__device__ float g_x[NB * NSEQ * DIN];
__device__ float g_w[DIN * DIN];

__device__ __forceinline__ unsigned f2tf(float f) {
    unsigned u; asm("cvt.rna.tf32.f32 %0, %1;" : "=r"(u) : "f"(f)); return u;
}

#if defined(__CUDA_ARCH_FEAT_SM103_ALL) || defined(__CUDA_ARCH_SPECIFIC__) || !defined(__CUDA_ARCH__)
#define HAS_TCGEN05 1
#else
#define HAS_TCGEN05 0
#endif

#define IDESC_TF32 ((1u<<4) | (2u<<7) | (2u<<10) | (8u<<17) | (8u<<24))  // f32 acc, tf32 a/b, N=64, M=128

#if HAS_TCGEN05
__device__ __forceinline__ unsigned sw128(unsigned b) { return b ^ ((b >> 3) & 0x70); }
__device__ __forceinline__ unsigned long long mk_desc(unsigned addr) {
    return 0x4000404000010000ULL | (unsigned long long)((addr >> 4) & 0x3FFF);
}
__device__ __forceinline__ unsigned elect1() {
    unsigned p;
    asm volatile("{\n\t.reg .pred p;\n\telect.sync _|p, 0xFFFFFFFF;\n\t"
                 "selp.b32 %0, 1, 0, p;\n\t}" : "=r"(p));
    return p;
}
__device__ __forceinline__ void mma_tf32_ss(unsigned dtmem, unsigned long long ad,
                                            unsigned long long bd, unsigned en) {
    asm volatile("{\n\t.reg .pred p;\n\tsetp.ne.u32 p, %4, 0;\n\t"
                 "tcgen05.mma.cta_group::1.kind::tf32 [%0], %1, %2, %3, p;\n\t}"
                 :: "r"(dtmem), "l"(ad), "l"(bd), "r"(IDESC_TF32), "r"(en) : "memory");
}
__device__ __forceinline__ void mbar_wait(unsigned mbar, unsigned parity) {
    asm volatile("{\n\t.reg .pred P1;\n\t"
                 "WL_%=:\n\t"
                 "mbarrier.try_wait.parity.acquire.cta.shared::cta.b64 P1, [%0], %1, 0x989680;\n\t"
                 "@P1 bra.uni WD_%=;\n\t"
                 "bra.uni WL_%=;\n\t"
                 "WD_%=:\n\t}" :: "r"(mbar), "r"(parity) : "memory");
}
__device__ __forceinline__ float ex2(float x) {
    float r; asm("ex2.approx.ftz.f32 %0, %1;" : "=f"(r) : "f"(x)); return r;
}
#define TCLD32(r, a) \
    asm volatile("tcgen05.ld.sync.aligned.32x32b.x32.b32 " \
        "{%0,%1,%2,%3,%4,%5,%6,%7,%8,%9,%10,%11,%12,%13,%14,%15," \
        "%16,%17,%18,%19,%20,%21,%22,%23,%24,%25,%26,%27,%28,%29,%30,%31}, [%32];" \
        : "=r"((r)[0]),"=r"((r)[1]),"=r"((r)[2]),"=r"((r)[3]),"=r"((r)[4]),"=r"((r)[5]),"=r"((r)[6]),"=r"((r)[7]), \
          "=r"((r)[8]),"=r"((r)[9]),"=r"((r)[10]),"=r"((r)[11]),"=r"((r)[12]),"=r"((r)[13]),"=r"((r)[14]),"=r"((r)[15]), \
          "=r"((r)[16]),"=r"((r)[17]),"=r"((r)[18]),"=r"((r)[19]),"=r"((r)[20]),"=r"((r)[21]),"=r"((r)[22]),"=r"((r)[23]), \
          "=r"((r)[24]),"=r"((r)[25]),"=r"((r)[26]),"=r"((r)[27]),"=r"((r)[28]),"=r"((r)[29]),"=r"((r)[30]),"=r"((r)[31]) \
        : "r"(a))
#endif

// ---------------------------------------------------------------------------
// Kernel 0: one-shot tf32-rna rounding, 2 float4s per thread (MLP=2).
// 933888 float4s (x: 786432, Wq: 147456); grid 1824 x 256.
// ---------------------------------------------------------------------------
__global__ __launch_bounds__(256) void round_inputs(const float* __restrict__ x,
                                                    const float* __restrict__ Wq) {
    int i = blockIdx.x * 256 + threadIdx.x;
    #pragma unroll
    for (int r = 0; r < 2; ++r, i += 466944) {
        float4 v = (i < 786432) ? ((const float4*)x)[i]
                                : ((const float4*)Wq)[i - 786432];
        float4 o;
        o.x = __uint_as_float(f2tf(v.x)); o.y = __uint_as_float(f2tf(v.y));
        o.z = __uint_as_float(f2tf(v.z)); o.w = __uint_as_float(f2tf(v.w));
        if (i < 786432) ((float4*)g_x)[i] = o;
        else            ((float4*)g_w)[i - 786432] = o;
    }
}

// ---------------------------------------------------------------------------
// Kernel 1: qkv projection via tcgen05 on pre-rounded g_x/g_w.
// grid (32, 12), 256 threads, double-buffered K=64 chunks.
// ---------------------------------------------------------------------------
#define GOFF_TMEM 0
#define GOFF_MB   8
#define GOFF_A0   1024
#define GOFF_A1   (GOFF_A0 + 32768)
#define GOFF_B0   (GOFF_A1 + 32768)
#define GOFF_B1   (GOFF_B0 + 16384)
#define GEMM_SMEM (GOFF_B1 + 16384)   // 99328 B

__global__ __launch_bounds__(256, 2) void qkv_gemm() {
    const int tid = threadIdx.x;
    const int m0 = blockIdx.x * 128;
    const int head = blockIdx.y;
    const int n0 = head * 64;

#if HAS_TCGEN05
    extern __shared__ char smem[];
    const unsigned sb = (unsigned)__cvta_generic_to_shared(smem);
    const int wid = tid >> 5;

    if (wid == 0) {
        asm volatile("tcgen05.alloc.cta_group::1.sync.aligned.shared::cta.b32 [%0], %1;"
                     :: "r"(sb + GOFF_TMEM), "r"(64u) : "memory");
        asm volatile("tcgen05.relinquish_alloc_permit.cta_group::1.sync.aligned;");
    }
    if (tid == 0)
        asm volatile("mbarrier.init.shared.b64 [%0], 1;" :: "r"(sb + GOFF_MB) : "memory");
    __syncthreads();
    unsigned tb;
    asm volatile("ld.shared.b32 %0, [%1];" : "=r"(tb) : "r"(sb + GOFF_TMEM));

    const unsigned aoffs[2] = {GOFF_A0, GOFF_A1};
    const unsigned boffs[2] = {GOFF_B0, GOFF_B1};

    auto load_chunk = [&](int kk) {
        const int k0 = kk * 64;
        const unsigned ab = sb + aoffs[kk & 1], bb = sb + boffs[kk & 1];
        #pragma unroll
        for (int i = 0; i < 8; ++i) {                // A: 2048 16B chunks / 256 thr
            int idx = tid + i * 256;
            int row = idx >> 4, c = idx & 15;
            unsigned dst = ab + (c >> 3) * 16384 + sw128(row * 128 + (c & 7) * 16);
            asm volatile("cp.async.cg.shared.global [%0], [%1], 16;"
                         :: "r"(dst), "l"(&g_x[(size_t)(m0 + row) * DIN + k0 + c * 4]));
        }
        #pragma unroll
        for (int i = 0; i < 4; ++i) {                // B: 1024 16B chunks
            int idx = tid + i * 256;
            int row = idx >> 4, c = idx & 15;
            unsigned dst = bb + (c >> 3) * 8192 + sw128(row * 128 + (c & 7) * 16);
            asm volatile("cp.async.cg.shared.global [%0], [%1], 16;"
                         :: "r"(dst), "l"(&g_w[(size_t)(n0 + row) * DIN + k0 + c * 4]));
        }
        asm volatile("cp.async.commit_group;");
    };

    load_chunk(0);
    load_chunk(1);

    for (int kk = 0; kk < 12; ++kk) {
        if (kk < 11) asm volatile("cp.async.wait_group 1;");
        else         asm volatile("cp.async.wait_group 0;");
        __syncthreads();
        asm volatile("fence.proxy.async.shared::cta;" ::: "memory");

        if (wid == 0 && elect1()) {
            const unsigned long long ad = mk_desc(sb + aoffs[kk & 1]);
            const unsigned long long bd = mk_desc(sb + boffs[kk & 1]);
            #pragma unroll
            for (int k8 = 0; k8 < 8; ++k8) {
                unsigned ao = (k8 >> 2) * 1024 + (k8 & 3) * 2;
                unsigned bo = (k8 >> 2) * 512  + (k8 & 3) * 2;
                mma_tf32_ss(tb, ad + ao, bd + bo, (kk > 0) || (k8 > 0));
            }
            asm volatile("tcgen05.commit.cta_group::1.mbarrier::arrive::one.shared::cluster.b64 [%0];"
                         :: "r"(sb + GOFF_MB) : "memory");
        }
        mbar_wait(sb + GOFF_MB, kk & 1);
        if (kk + 2 < 12) load_chunk(kk + 2);
    }

    // epilogue: warps 0-3 cols 0-31, warps 4-7 cols 32-63; 32 values/thread
    asm volatile("tcgen05.fence::after_thread_sync;" ::: "memory");
    const int j0 = (tid >> 7) * 32;
    unsigned dr[32];
    TCLD32(dr, tb + j0);
    asm volatile("tcgen05.wait::ld.sync.aligned;" ::: "memory");
    asm volatile("tcgen05.fence::before_thread_sync;" ::: "memory");

    {
        int m = m0 + (tid & 127);
        int b = m >> 11, q = m & 2047;
        float* dst = &g_h[((size_t)(b * NH + head) * NSEQ + q) * HD + j0];
        #pragma unroll
        for (int j = 0; j < 8; ++j) {
            float4 v;
            v.x = __uint_as_float(f2tf(__uint_as_float(dr[4*j  ])));
            v.y = __uint_as_float(f2tf(__uint_as_float(dr[4*j+1])));
            v.z = __uint_as_float(f2tf(__uint_as_float(dr[4*j+2])));
            v.w = __uint_as_float(f2tf(__uint_as_float(dr[4*j+3])));
            *(float4*)&dst[4*j] = v;
        }
    }
    __syncthreads();
    if (wid == 0)
        asm volatile("tcgen05.dealloc.cta_group::1.sync.aligned.b32 %0, %1;"
                     :: "r"(tb), "r"(64u));
#else
    // scalar fallback (non-103a pass only; correct, never runs)
    int m = m0 + (tid & 127);
    int j0 = (tid >> 7) * 32;
    int b = m >> 11, q = m & 2047;
    float* dst = &g_h[((size_t)(b * NH + head) * NSEQ + q) * HD];
    for (int c = j0; c < j0 + 32; ++c) {
        float s = 0.f;
        for (int k = 0; k < DIN; ++k)
            s += g_x[(size_t)m * DIN + k] * g_w[(size_t)(n0 + c) * DIN + k];
        dst[c] = __uint_as_float(f2tf(s));
    }
#endif
}

// ---------------------------------------------------------------------------
// Kernel 2: tcgen05 causal flash attention, 256 threads.
// Warps 0-3 own S/O cols 0-31, warps 4-7 cols 32-63 (32 elements/thread).
// ---------------------------------------------------------------------------
#define OFF_TMEM 0
#define OFF_MBS  8
#define OFF_MBO  16
#define OFF_Q    1024
#define OFF_K    (OFF_Q  + 32768)
#define OFF_KT   (OFF_K  + 16384)
#define OFF_P    (OFF_KT + 16384)
#define ATTN_SMEM (OFF_P + 32768)    // 99328 B

__global__ __launch_bounds__(256, 2) void attn_kernel(float* __restrict__ out) {
    const int tid = threadIdx.x;
    const int qt = 15 - ((int)blockIdx.x / 24);   // work-sorted
    const int bh = (int)blockIdx.x % 24;
    const float* hbase = &g_h[(size_t)bh * NSEQ * HD];
    const int q0 = qt * 128;
    const float sc2 = 0.18033688011112042f;       // log2(e)/8

#if HAS_TCGEN05
    extern __shared__ char smem[];
    const unsigned sb = (unsigned)__cvta_generic_to_shared(smem);
    const int wid = tid >> 5;
    const int rtid = tid & 127;                   // q-row this thread owns
    const int j0 = (tid >> 7) * 32;               // column base (0 or 32)
    const int nkt = 2 * qt + 2;

    if (wid == 0) {
        asm volatile("tcgen05.alloc.cta_group::1.sync.aligned.shared::cta.b32 [%0], %1;"
                     :: "r"(sb + OFF_TMEM), "r"(128u) : "memory");
        asm volatile("tcgen05.relinquish_alloc_permit.cta_group::1.sync.aligned;");
    }
    if (tid == 0) {
        asm volatile("mbarrier.init.shared.b64 [%0], 1;" :: "r"(sb + OFF_MBS) : "memory");
        asm volatile("mbarrier.init.shared.b64 [%0], 1;" :: "r"(sb + OFF_MBO) : "memory");
    }
    __syncthreads();
    unsigned tb;
    asm volatile("ld.shared.b32 %0, [%1];" : "=r"(tb) : "r"(sb + OFF_TMEM));

    #pragma unroll
    for (int i = 0; i < 8; ++i) {                 // Q: 2048 chunks / 256 thr
        int idx = tid + i * 256;
        int row = idx >> 4, c = idx & 15;
        unsigned dst = sb + OFF_Q + (c >> 3) * 16384 + sw128(row * 128 + (c & 7) * 16);
        asm volatile("cp.async.cg.shared.global [%0], [%1], 16;"
                     :: "r"(dst), "l"(hbase + (size_t)(q0 + row) * HD + c * 4));
    }
    #pragma unroll
    for (int i = 0; i < 4; ++i) {                 // K: 1024 chunks
        int idx = tid + i * 256;
        int row = idx >> 4, c = idx & 15;
        unsigned dst = sb + OFF_K + (c >> 3) * 8192 + sw128(row * 128 + (c & 7) * 16);
        asm volatile("cp.async.cg.shared.global [%0], [%1], 16;"
                     :: "r"(dst), "l"(hbase + (size_t)row * HD + c * 4));
    }
    asm volatile("cp.async.commit_group;");

    const unsigned long long qdesc  = mk_desc(sb + OFF_Q);
    const unsigned long long kdesc  = mk_desc(sb + OFF_K);
    const unsigned long long ktdesc = mk_desc(sb + OFF_KT);
    const unsigned long long pdesc  = mk_desc(sb + OFF_P);
    float lrow = 0.f;                              // per-thread partial (32 cols)
    int ps = 0, po = 0;

    for (int kt = 0; kt < nkt; ++kt) {
        asm volatile("cp.async.wait_group 0;");
        __syncthreads();
        asm volatile("fence.proxy.async.shared::cta;" ::: "memory");

        // ---- S = Q K^T into TMEM cols 0..63 ----
        if (wid == 0 && elect1()) {
            #pragma unroll
            for (int k8 = 0; k8 < 8; ++k8) {
                unsigned qoff = (k8 >> 2) * 1024 + (k8 & 3) * 2;
                unsigned koff = (k8 >> 2) * 512  + (k8 & 3) * 2;
                mma_tf32_ss(tb, qdesc + qoff, kdesc + koff, k8 > 0);
            }
            asm volatile("tcgen05.commit.cta_group::1.mbarrier::arrive::one.shared::cluster.b64 [%0];"
                         :: "r"(sb + OFF_MBS) : "memory");
        }

        if (kt > 0) { mbar_wait(sb + OFF_MBO, po); po ^= 1; }

        // ---- transpose K -> KT: thread owns (col td, 16 keys) ----
        {
            const int td = tid & 63, kq = tid >> 6;   // kq 0..3
            const int tk0 = kq * 16;
            float v[16];
            #pragma unroll
            for (int i = 0; i < 16; ++i) {
                unsigned a = sb + OFF_K + (td >> 5) * 8192
                           + sw128((tk0 + i) * 128 + (td & 31) * 4);
                asm volatile("ld.shared.b32 %0, [%1];" : "=f"(v[i]) : "r"(a));
            }
            #pragma unroll
            for (int j = 0; j < 4; ++j) {
                unsigned a = sb + OFF_KT + (kq >> 1) * 8192
                           + sw128(td * 128 + (kq & 1) * 64 + j * 16);
                asm volatile("st.shared.v4.b32 [%0], {%1,%2,%3,%4};"
                             :: "r"(a), "f"(v[4*j]), "f"(v[4*j+1]), "f"(v[4*j+2]), "f"(v[4*j+3])
                             : "memory");
            }
        }

        // ---- S done + transpose reads done -> prefetch K(kt+1) early ----
        mbar_wait(sb + OFF_MBS, ps); ps ^= 1;
        __syncthreads();
        if (kt + 1 < nkt) {
            #pragma unroll
            for (int i = 0; i < 4; ++i) {
                int idx = tid + i * 256;
                int row = idx >> 4, c = idx & 15;
                unsigned dst = sb + OFF_K + (c >> 3) * 8192 + sw128(row * 128 + (c & 7) * 16);
                asm volatile("cp.async.cg.shared.global [%0], [%1], 16;"
                             :: "r"(dst), "l"(hbase + (size_t)((kt + 1) * 64 + row) * HD + c * 4));
            }
            asm volatile("cp.async.commit_group;");
        }

        // ---- read 32 S cols, softmax ----
        asm volatile("tcgen05.fence::after_thread_sync;" ::: "memory");
        unsigned sr[32];
        TCLD32(sr, tb + j0);
        asm volatile("tcgen05.wait::ld.sync.aligned;" ::: "memory");
        asm volatile("tcgen05.fence::before_thread_sync;" ::: "memory");

        const int qg = q0 + rtid, kbase = kt * 64 + j0;
        float p[32], rs = 0.f;
        if (kbase + 31 <= qg) {
            #pragma unroll
            for (int j = 0; j < 32; ++j) {
                float pj = ex2(__uint_as_float(sr[j]) * sc2);
                p[j] = pj; rs += pj;
            }
        } else {
            #pragma unroll
            for (int j = 0; j < 32; ++j) {
                float pj = (kbase + j > qg) ? 0.f : ex2(__uint_as_float(sr[j]) * sc2);
                p[j] = pj; rs += pj;
            }
        }
        lrow += rs;

        // ---- stage P (32 floats -> one slab, 8 v4 stores) ----
        #pragma unroll
        for (int c = 0; c < 8; ++c) {
            unsigned a = sb + OFF_P + (tid >> 7) * 16384 + sw128(rtid * 128 + c * 16);
            asm volatile("st.shared.v4.b32 [%0], {%1,%2,%3,%4};"
                         :: "r"(a), "r"(f2tf(p[4*c])), "r"(f2tf(p[4*c+1])),
                            "r"(f2tf(p[4*c+2])), "r"(f2tf(p[4*c+3])) : "memory");
        }
        __syncthreads();                     // P + KT visible to all
        asm volatile("fence.proxy.async.shared::cta;" ::: "memory");

        // ---- O += P·KT into TMEM cols 64..127 ----
        if (wid == 0 && elect1()) {
            #pragma unroll
            for (int k8 = 0; k8 < 8; ++k8) {
                unsigned poff  = (k8 >> 2) * 1024 + (k8 & 3) * 2;
                unsigned ktoff = (k8 >> 2) * 512  + (k8 & 3) * 2;
                mma_tf32_ss(tb + 64, pdesc + poff, ktdesc + ktoff, (kt > 0) || (k8 > 0));
            }
            asm volatile("tcgen05.commit.cta_group::1.mbarrier::arrive::one.shared::cluster.b64 [%0];"
                         :: "r"(sb + OFF_MBO) : "memory");
        }
    }

    // ---- epilogue ----
    mbar_wait(sb + OFF_MBO, po);
    // combine lrow partials (P region is dead now)
    float* lp = (float*)(smem + OFF_P);
    lp[tid] = lrow;
    __syncthreads();
    const float inv = 1.0f / (lp[rtid] + lp[rtid + 128]);

    asm volatile("tcgen05.fence::after_thread_sync;" ::: "memory");
    unsigned orr[32];
    TCLD32(orr, tb + 64 + j0);
    asm volatile("tcgen05.wait::ld.sync.aligned;" ::: "memory");
    asm volatile("tcgen05.fence::before_thread_sync;" ::: "memory");

    float* Os = (float*)(smem + 1024);            // 64 x 132 staging (overlays Q/K)
    #pragma unroll
    for (int j = 0; j < 32; ++j)
        Os[(j0 + j) * 132 + rtid] = __uint_as_float(orr[j]) * inv;
    __syncthreads();
    float* obase = out + (size_t)bh * HD * NSEQ + q0;
    #pragma unroll
    for (int i = 0; i < 8; ++i) {                 // 2048 float4 = 64x128 tile
        int idx = tid + i * 256;
        int d = idx >> 5, q4 = (idx & 31) * 4;
        *(float4*)&obase[(size_t)d * NSEQ + q4] = *(float4*)&Os[d * 132 + q4];
    }
    __syncthreads();
    if (wid == 0)
        asm volatile("tcgen05.dealloc.cta_group::1.sync.aligned.b32 %0, %1;"
                     :: "r"(tb), "r"(128u));
#else
    // scalar fallback (non-103a pass only; correct, never runs)
    if (tid < 128) {
        const int qg = q0 + tid;
        const float* hq = hbase + (size_t)qg * HD;
        float o[HD];
        #pragma unroll
        for (int d = 0; d < HD; ++d) o[d] = 0.f;
        float l = 0.f;
        for (int k = 0; k <= qg; ++k) {
            const float* hk = hbase + (size_t)k * HD;
            float s = 0.f;
            #pragma unroll
            for (int d = 0; d < HD; ++d) s += hq[d] * hk[d];
            float pv = exp2f(s * sc2);
            l += pv;
            #pragma unroll
            for (int d = 0; d < HD; ++d) o[d] += pv * hk[d];
        }
        float* obase = out + (size_t)bh * HD * NSEQ + q0;
        float inv = 1.0f / l;
        #pragma unroll
        for (int d = 0; d < HD; ++d)
            obase[(size_t)d * NSEQ + tid] = o[d] * inv;
    }
#endif
}

// ---------------------------------------------------------------------------
extern "C" void kernel_launch(void* const* d_in, const int* in_sizes, int n_in,
                              void* d_out, int out_size) {
    const float* x  = (const float*)d_in[0];
    const float* Wq = (const float*)d_in[1];
    float* out = (float*)d_out;

    cudaFuncSetAttribute(qkv_gemm, cudaFuncAttributeMaxDynamicSharedMemorySize, GEMM_SMEM);
    cudaFuncSetAttribute(attn_kernel, cudaFuncAttributeMaxDynamicSharedMemorySize, ATTN_SMEM);

    round_inputs<<<1824, 256>>>(x, Wq);
    qkv_gemm<<<dim3(32, 12), 256, GEMM_SMEM>>>();
    attn_kernel<<<384, 256, ATTN_SMEM>>>(out);
}

// round 17
// speedup vs baseline: 2.9178x; 1.0282x over previous
#include <cuda_runtime.h>

#define NH   12
#define HD   64
#define NSEQ 2048
#define NB   2
#define DIN  768

// scratch: h = x @ Wq^T (tf32-exact), laid out [b][head][q][d]
__device__ float g_h[NB * NH * NSEQ * HD];
// tf32-rna pre-rounded copies of the inputs
__device__ float g_x[NB * NSEQ * DIN];
__device__ float g_w[DIN * DIN];

__device__ __forceinline__ unsigned f2tf(float f) {
    unsigned u; asm("cvt.rna.tf32.f32 %0, %1;" : "=r"(u) : "f"(f)); return u;
}

#if defined(__CUDA_ARCH_FEAT_SM103_ALL) || defined(__CUDA_ARCH_SPECIFIC__) || !defined(__CUDA_ARCH__)
#define HAS_TCGEN05 1
#else
#define HAS_TCGEN05 0
#endif

#define IDESC_TF32 ((1u<<4) | (2u<<7) | (2u<<10) | (8u<<17) | (8u<<24))  // f32 acc, tf32 a/b, N=64, M=128

#if HAS_TCGEN05
__device__ __forceinline__ unsigned sw128(unsigned b) { return b ^ ((b >> 3) & 0x70); }
__device__ __forceinline__ unsigned long long mk_desc(unsigned addr) {
    return 0x4000404000010000ULL | (unsigned long long)((addr >> 4) & 0x3FFF);
}
__device__ __forceinline__ unsigned elect1() {
    unsigned p;
    asm volatile("{\n\t.reg .pred p;\n\telect.sync _|p, 0xFFFFFFFF;\n\t"
                 "selp.b32 %0, 1, 0, p;\n\t}" : "=r"(p));
    return p;
}
__device__ __forceinline__ void mma_tf32_ss(unsigned dtmem, unsigned long long ad,
                                            unsigned long long bd, unsigned en) {
    asm volatile("{\n\t.reg .pred p;\n\tsetp.ne.u32 p, %4, 0;\n\t"
                 "tcgen05.mma.cta_group::1.kind::tf32 [%0], %1, %2, %3, p;\n\t}"
                 :: "r"(dtmem), "l"(ad), "l"(bd), "r"(IDESC_TF32), "r"(en) : "memory");
}
__device__ __forceinline__ void mma_tf32_ts(unsigned dtmem, unsigned atmem,
                                            unsigned long long bd, unsigned en) {
    asm volatile("{\n\t.reg .pred p;\n\tsetp.ne.u32 p, %4, 0;\n\t"
                 "tcgen05.mma.cta_group::1.kind::tf32 [%0], [%1], %2, %3, p;\n\t}"
                 :: "r"(dtmem), "r"(atmem), "l"(bd), "r"(IDESC_TF32), "r"(en) : "memory");
}
__device__ __forceinline__ void mbar_wait(unsigned mbar, unsigned parity) {
    asm volatile("{\n\t.reg .pred P1;\n\t"
                 "WL_%=:\n\t"
                 "mbarrier.try_wait.parity.acquire.cta.shared::cta.b64 P1, [%0], %1, 0x989680;\n\t"
                 "@P1 bra.uni WD_%=;\n\t"
                 "bra.uni WL_%=;\n\t"
                 "WD_%=:\n\t}" :: "r"(mbar), "r"(parity) : "memory");
}
__device__ __forceinline__ float ex2(float x) {
    float r; asm("ex2.approx.ftz.f32 %0, %1;" : "=f"(r) : "f"(x)); return r;
}
#define TCLD32(r, a) \
    asm volatile("tcgen05.ld.sync.aligned.32x32b.x32.b32 " \
        "{%0,%1,%2,%3,%4,%5,%6,%7,%8,%9,%10,%11,%12,%13,%14,%15," \
        "%16,%17,%18,%19,%20,%21,%22,%23,%24,%25,%26,%27,%28,%29,%30,%31}, [%32];" \
        : "=r"((r)[0]),"=r"((r)[1]),"=r"((r)[2]),"=r"((r)[3]),"=r"((r)[4]),"=r"((r)[5]),"=r"((r)[6]),"=r"((r)[7]), \
          "=r"((r)[8]),"=r"((r)[9]),"=r"((r)[10]),"=r"((r)[11]),"=r"((r)[12]),"=r"((r)[13]),"=r"((r)[14]),"=r"((r)[15]), \
          "=r"((r)[16]),"=r"((r)[17]),"=r"((r)[18]),"=r"((r)[19]),"=r"((r)[20]),"=r"((r)[21]),"=r"((r)[22]),"=r"((r)[23]), \
          "=r"((r)[24]),"=r"((r)[25]),"=r"((r)[26]),"=r"((r)[27]),"=r"((r)[28]),"=r"((r)[29]),"=r"((r)[30]),"=r"((r)[31]) \
        : "r"(a))
#define TCST32(a, r) \
    asm volatile("tcgen05.st.sync.aligned.32x32b.x32.b32 [%0], " \
        "{%1,%2,%3,%4,%5,%6,%7,%8,%9,%10,%11,%12,%13,%14,%15,%16," \
        "%17,%18,%19,%20,%21,%22,%23,%24,%25,%26,%27,%28,%29,%30,%31,%32};" \
        :: "r"(a), \
           "r"((r)[0]),"r"((r)[1]),"r"((r)[2]),"r"((r)[3]),"r"((r)[4]),"r"((r)[5]),"r"((r)[6]),"r"((r)[7]), \
           "r"((r)[8]),"r"((r)[9]),"r"((r)[10]),"r"((r)[11]),"r"((r)[12]),"r"((r)[13]),"r"((r)[14]),"r"((r)[15]), \
           "r"((r)[16]),"r"((r)[17]),"r"((r)[18]),"r"((r)[19]),"r"((r)[20]),"r"((r)[21]),"r"((r)[22]),"r"((r)[23]), \
           "r"((r)[24]),"r"((r)[25]),"r"((r)[26]),"r"((r)[27]),"r"((r)[28]),"r"((r)[29]),"r"((r)[30]),"r"((r)[31]) \
        : "memory")
#endif

// ---------------------------------------------------------------------------
// Kernel 0: one-shot tf32-rna rounding (unchanged from R16)
// ---------------------------------------------------------------------------
__global__ __launch_bounds__(256) void round_inputs(const float* __restrict__ x,
                                                    const float* __restrict__ Wq) {
    int i = blockIdx.x * 256 + threadIdx.x;
    #pragma unroll
    for (int r = 0; r < 2; ++r, i += 466944) {
        float4 v = (i < 786432) ? ((const float4*)x)[i]
                                : ((const float4*)Wq)[i - 786432];
        float4 o;
        o.x = __uint_as_float(f2tf(v.x)); o.y = __uint_as_float(f2tf(v.y));
        o.z = __uint_as_float(f2tf(v.z)); o.w = __uint_as_float(f2tf(v.w));
        if (i < 786432) ((float4*)g_x)[i] = o;
        else            ((float4*)g_w)[i - 786432] = o;
    }
}

// ---------------------------------------------------------------------------
// Kernel 1: qkv projection via tcgen05 (unchanged from R16)
// ---------------------------------------------------------------------------
#define GOFF_TMEM 0
#define GOFF_MB   8
#define GOFF_A0   1024
#define GOFF_A1   (GOFF_A0 + 32768)
#define GOFF_B0   (GOFF_A1 + 32768)
#define GOFF_B1   (GOFF_B0 + 16384)
#define GEMM_SMEM (GOFF_B1 + 16384)   // 99328 B

__global__ __launch_bounds__(256, 2) void qkv_gemm() {
    const int tid = threadIdx.x;
    const int m0 = blockIdx.x * 128;
    const int head = blockIdx.y;
    const int n0 = head * 64;

#if HAS_TCGEN05
    extern __shared__ char smem[];
    const unsigned sb = (unsigned)__cvta_generic_to_shared(smem);
    const int wid = tid >> 5;

    if (wid == 0) {
        asm volatile("tcgen05.alloc.cta_group::1.sync.aligned.shared::cta.b32 [%0], %1;"
                     :: "r"(sb + GOFF_TMEM), "r"(64u) : "memory");
        asm volatile("tcgen05.relinquish_alloc_permit.cta_group::1.sync.aligned;");
    }
    if (tid == 0)
        asm volatile("mbarrier.init.shared.b64 [%0], 1;" :: "r"(sb + GOFF_MB) : "memory");
    __syncthreads();
    unsigned tb;
    asm volatile("ld.shared.b32 %0, [%1];" : "=r"(tb) : "r"(sb + GOFF_TMEM));

    const unsigned aoffs[2] = {GOFF_A0, GOFF_A1};
    const unsigned boffs[2] = {GOFF_B0, GOFF_B1};

    auto load_chunk = [&](int kk) {
        const int k0 = kk * 64;
        const unsigned ab = sb + aoffs[kk & 1], bb = sb + boffs[kk & 1];
        #pragma unroll
        for (int i = 0; i < 8; ++i) {
            int idx = tid + i * 256;
            int row = idx >> 4, c = idx & 15;
            unsigned dst = ab + (c >> 3) * 16384 + sw128(row * 128 + (c & 7) * 16);
            asm volatile("cp.async.cg.shared.global [%0], [%1], 16;"
                         :: "r"(dst), "l"(&g_x[(size_t)(m0 + row) * DIN + k0 + c * 4]));
        }
        #pragma unroll
        for (int i = 0; i < 4; ++i) {
            int idx = tid + i * 256;
            int row = idx >> 4, c = idx & 15;
            unsigned dst = bb + (c >> 3) * 8192 + sw128(row * 128 + (c & 7) * 16);
            asm volatile("cp.async.cg.shared.global [%0], [%1], 16;"
                         :: "r"(dst), "l"(&g_w[(size_t)(n0 + row) * DIN + k0 + c * 4]));
        }
        asm volatile("cp.async.commit_group;");
    };

    load_chunk(0);
    load_chunk(1);

    for (int kk = 0; kk < 12; ++kk) {
        if (kk < 11) asm volatile("cp.async.wait_group 1;");
        else         asm volatile("cp.async.wait_group 0;");
        __syncthreads();
        asm volatile("fence.proxy.async.shared::cta;" ::: "memory");

        if (wid == 0 && elect1()) {
            const unsigned long long ad = mk_desc(sb + aoffs[kk & 1]);
            const unsigned long long bd = mk_desc(sb + boffs[kk & 1]);
            #pragma unroll
            for (int k8 = 0; k8 < 8; ++k8) {
                unsigned ao = (k8 >> 2) * 1024 + (k8 & 3) * 2;
                unsigned bo = (k8 >> 2) * 512  + (k8 & 3) * 2;
                mma_tf32_ss(tb, ad + ao, bd + bo, (kk > 0) || (k8 > 0));
            }
            asm volatile("tcgen05.commit.cta_group::1.mbarrier::arrive::one.shared::cluster.b64 [%0];"
                         :: "r"(sb + GOFF_MB) : "memory");
        }
        mbar_wait(sb + GOFF_MB, kk & 1);
        if (kk + 2 < 12) load_chunk(kk + 2);
    }

    asm volatile("tcgen05.fence::after_thread_sync;" ::: "memory");
    const int j0g = (tid >> 7) * 32;
    unsigned dr[32];
    TCLD32(dr, tb + j0g);
    asm volatile("tcgen05.wait::ld.sync.aligned;" ::: "memory");
    asm volatile("tcgen05.fence::before_thread_sync;" ::: "memory");

    {
        int m = m0 + (tid & 127);
        int b = m >> 11, q = m & 2047;
        float* dst = &g_h[((size_t)(b * NH + head) * NSEQ + q) * HD + j0g];
        #pragma unroll
        for (int j = 0; j < 8; ++j) {
            float4 v;
            v.x = __uint_as_float(f2tf(__uint_as_float(dr[4*j  ])));
            v.y = __uint_as_float(f2tf(__uint_as_float(dr[4*j+1])));
            v.z = __uint_as_float(f2tf(__uint_as_float(dr[4*j+2])));
            v.w = __uint_as_float(f2tf(__uint_as_float(dr[4*j+3])));
            *(float4*)&dst[4*j] = v;
        }
    }
    __syncthreads();
    if (wid == 0)
        asm volatile("tcgen05.dealloc.cta_group::1.sync.aligned.b32 %0, %1;"
                     :: "r"(tb), "r"(64u));
#else
    int m = m0 + (tid & 127);
    int j0g = (tid >> 7) * 32;
    int b = m >> 11, q = m & 2047;
    float* dst = &g_h[((size_t)(b * NH + head) * NSEQ + q) * HD];
    for (int c = j0g; c < j0g + 32; ++c) {
        float s = 0.f;
        for (int k = 0; k < DIN; ++k)
            s += g_x[(size_t)m * DIN + k] * g_w[(size_t)(n0 + c) * DIN + k];
        dst[c] = __uint_as_float(f2tf(s));
    }
#endif
}

// ---------------------------------------------------------------------------
// Kernel 2: pipelined tcgen05 flash attention.
// TMEM: S0@0, S1@64, O@128, Q@192 (alloc 256). Q loaded once via tcgen05.st;
// S via TS-mode mma (A in TMEM). 3 rotating K smem buffers; softmax(kt)
// overlaps S(kt+1) on the tensor pipe.
// ---------------------------------------------------------------------------
#define OFF_TMEM 0
#define OFF_MBS  8
#define OFF_MBO  16
#define OFF_K0   1024
#define OFF_K1   (OFF_K0 + 16384)
#define OFF_K2   (OFF_K1 + 16384)
#define OFF_KT   (OFF_K2 + 16384)
#define OFF_P    (OFF_KT + 16384)
#define ATTN_SMEM (OFF_P + 32768)    // 99328 B

__global__ __launch_bounds__(256, 2) void attn_kernel(float* __restrict__ out) {
    const int tid = threadIdx.x;
    const int qt = 15 - ((int)blockIdx.x / 24);   // work-sorted
    const int bh = (int)blockIdx.x % 24;
    const float* hbase = &g_h[(size_t)bh * NSEQ * HD];
    const int q0 = qt * 128;
    const float sc2 = 0.18033688011112042f;       // log2(e)/8

#if HAS_TCGEN05
    extern __shared__ char smem[];
    const unsigned sb = (unsigned)__cvta_generic_to_shared(smem);
    const int wid = tid >> 5;
    const int rtid = tid & 127;
    const int j0 = (tid >> 7) * 32;
    const int nkt = 2 * qt + 2;
    const unsigned koff_arr[3] = {OFF_K0, OFF_K1, OFF_K2};

    if (wid == 0) {
        asm volatile("tcgen05.alloc.cta_group::1.sync.aligned.shared::cta.b32 [%0], %1;"
                     :: "r"(sb + OFF_TMEM), "r"(256u) : "memory");
        asm volatile("tcgen05.relinquish_alloc_permit.cta_group::1.sync.aligned;");
    }
    if (tid == 0) {
        asm volatile("mbarrier.init.shared.b64 [%0], 1;" :: "r"(sb + OFF_MBS) : "memory");
        asm volatile("mbarrier.init.shared.b64 [%0], 1;" :: "r"(sb + OFF_MBO) : "memory");
    }
    __syncthreads();
    unsigned tb;
    asm volatile("ld.shared.b32 %0, [%1];" : "=r"(tb) : "r"(sb + OFF_TMEM));

    auto load_k = [&](int bi, int t) {
        const unsigned kb = sb + koff_arr[bi];
        #pragma unroll
        for (int i = 0; i < 4; ++i) {
            int idx = tid + i * 256;
            int row = idx >> 4, c = idx & 15;
            unsigned dst = kb + (c >> 3) * 8192 + sw128(row * 128 + (c & 7) * 16);
            asm volatile("cp.async.cg.shared.global [%0], [%1], 16;"
                         :: "r"(dst), "l"(hbase + (size_t)(t * 64 + row) * HD + c * 4));
        }
        asm volatile("cp.async.commit_group;");
    };

    // prologue: K(0), K(1) async; Q -> TMEM via tcgen05.st
    load_k(0, 0);
    if (nkt > 1) load_k(1, 1);
    {
        unsigned qr[32];
        const float4* qsrc = (const float4*)(hbase + (size_t)(q0 + rtid) * HD + j0);
        #pragma unroll
        for (int j = 0; j < 8; ++j) {
            float4 v = qsrc[j];
            qr[4*j  ] = __float_as_uint(v.x); qr[4*j+1] = __float_as_uint(v.y);
            qr[4*j+2] = __float_as_uint(v.z); qr[4*j+3] = __float_as_uint(v.w);
        }
        unsigned wo = ((unsigned)(rtid >> 5)) << 21;
        TCST32(tb + 192 + j0 + wo, qr);
        asm volatile("tcgen05.wait::st.sync.aligned;" ::: "memory");
    }
    asm volatile("tcgen05.fence::before_thread_sync;" ::: "memory");
    if (nkt > 1) asm volatile("cp.async.wait_group 1;");
    else         asm volatile("cp.async.wait_group 0;");
    __syncthreads();
    asm volatile("fence.proxy.async.shared::cta;" ::: "memory");

    const unsigned long long ktdesc = mk_desc(sb + OFF_KT);
    const unsigned long long pdesc  = mk_desc(sb + OFF_P);

    // issue S(0): TS-mode, A = Q in TMEM, B = K0
    if (wid == 0 && elect1()) {
        asm volatile("tcgen05.fence::after_thread_sync;" ::: "memory");
        const unsigned long long bd = mk_desc(sb + OFF_K0);
        #pragma unroll
        for (int k8 = 0; k8 < 8; ++k8) {
            unsigned bo = (k8 >> 2) * 512 + (k8 & 3) * 2;
            mma_tf32_ts(tb, tb + 192 + k8 * 8, bd + bo, k8 > 0);
        }
        asm volatile("tcgen05.commit.cta_group::1.mbarrier::arrive::one.shared::cluster.b64 [%0];"
                     :: "r"(sb + OFF_MBS) : "memory");
    }

    float lrow = 0.f;
    int ps = 0, po = 0;

    for (int kt = 0; kt < nkt; ++kt) {
        const int bufc = kt % 3, bufn = (kt + 1) % 3, buf2 = (kt + 2) % 3;

        // prefetch K(kt+2) into the free buffer (last read 1 iter ago)
        if (kt + 2 < nkt) load_k(buf2, kt + 2);

        // ---- S(kt) done ----
        mbar_wait(sb + OFF_MBS, ps); ps ^= 1;
        asm volatile("tcgen05.fence::after_thread_sync;" ::: "memory");
        unsigned sr[32];
        TCLD32(sr, tb + (kt & 1) * 64 + j0);
        asm volatile("tcgen05.wait::ld.sync.aligned;" ::: "memory");
        asm volatile("tcgen05.fence::before_thread_sync;" ::: "memory");

        // ---- O(kt-1) done -> KT and P free ----
        if (kt > 0) { mbar_wait(sb + OFF_MBO, po); po ^= 1; }

        // ---- transpose K[bufc] -> KT ----
        {
            const int td = tid & 63, kq = tid >> 6;
            const int tk0 = kq * 16;
            const unsigned kb = sb + koff_arr[bufc];
            float v[16];
            #pragma unroll
            for (int i = 0; i < 16; ++i) {
                unsigned a = kb + (td >> 5) * 8192
                           + sw128((tk0 + i) * 128 + (td & 31) * 4);
                asm volatile("ld.shared.b32 %0, [%1];" : "=f"(v[i]) : "r"(a));
            }
            #pragma unroll
            for (int j = 0; j < 4; ++j) {
                unsigned a = sb + OFF_KT + (kq >> 1) * 8192
                           + sw128(td * 128 + (kq & 1) * 64 + j * 16);
                asm volatile("st.shared.v4.b32 [%0], {%1,%2,%3,%4};"
                             :: "r"(a), "f"(v[4*j]), "f"(v[4*j+1]), "f"(v[4*j+2]), "f"(v[4*j+3])
                             : "memory");
            }
        }

        // K(kt+1) arrived everywhere, then issue S(kt+1) BEFORE softmax
        if (kt + 1 < nkt) {
            if (kt + 2 < nkt) asm volatile("cp.async.wait_group 1;");
            else              asm volatile("cp.async.wait_group 0;");
        }
        __syncthreads();
        asm volatile("fence.proxy.async.shared::cta;" ::: "memory");

        if (kt + 1 < nkt && wid == 0 && elect1()) {
            asm volatile("tcgen05.fence::after_thread_sync;" ::: "memory");
            const unsigned long long bd = mk_desc(sb + koff_arr[bufn]);
            const unsigned sdst = tb + ((kt + 1) & 1) * 64;
            #pragma unroll
            for (int k8 = 0; k8 < 8; ++k8) {
                unsigned bo = (k8 >> 2) * 512 + (k8 & 3) * 2;
                mma_tf32_ts(sdst, tb + 192 + k8 * 8, bd + bo, k8 > 0);
            }
            asm volatile("tcgen05.commit.cta_group::1.mbarrier::arrive::one.shared::cluster.b64 [%0];"
                         :: "r"(sb + OFF_MBS) : "memory");
        }

        // ---- softmax (overlaps S(kt+1) on the tensor pipe) ----
        const int qg = q0 + rtid, kbase = kt * 64 + j0;
        float p[32], rs = 0.f;
        if (kbase + 31 <= qg) {
            #pragma unroll
            for (int j = 0; j < 32; ++j) {
                float pj = ex2(__uint_as_float(sr[j]) * sc2);
                p[j] = pj; rs += pj;
            }
        } else {
            #pragma unroll
            for (int j = 0; j < 32; ++j) {
                float pj = (kbase + j > qg) ? 0.f : ex2(__uint_as_float(sr[j]) * sc2);
                p[j] = pj; rs += pj;
            }
        }
        lrow += rs;

        // ---- stage P ----
        #pragma unroll
        for (int c = 0; c < 8; ++c) {
            unsigned a = sb + OFF_P + (tid >> 7) * 16384 + sw128(rtid * 128 + c * 16);
            asm volatile("st.shared.v4.b32 [%0], {%1,%2,%3,%4};"
                         :: "r"(a), "r"(f2tf(p[4*c])), "r"(f2tf(p[4*c+1])),
                            "r"(f2tf(p[4*c+2])), "r"(f2tf(p[4*c+3])) : "memory");
        }
        __syncthreads();
        asm volatile("fence.proxy.async.shared::cta;" ::: "memory");

        // ---- O(kt) += P·KT ----
        if (wid == 0 && elect1()) {
            #pragma unroll
            for (int k8 = 0; k8 < 8; ++k8) {
                unsigned poff  = (k8 >> 2) * 1024 + (k8 & 3) * 2;
                unsigned ktoff = (k8 >> 2) * 512  + (k8 & 3) * 2;
                mma_tf32_ss(tb + 128, pdesc + poff, ktdesc + ktoff, (kt > 0) || (k8 > 0));
            }
            asm volatile("tcgen05.commit.cta_group::1.mbarrier::arrive::one.shared::cluster.b64 [%0];"
                         :: "r"(sb + OFF_MBO) : "memory");
        }
    }

    // ---- epilogue ----
    mbar_wait(sb + OFF_MBO, po);
    float* lp = (float*)(smem + OFF_P);
    lp[tid] = lrow;
    __syncthreads();
    const float inv = 1.0f / (lp[rtid] + lp[rtid + 128]);

    asm volatile("tcgen05.fence::after_thread_sync;" ::: "memory");
    unsigned orr[32];
    TCLD32(orr, tb + 128 + j0);
    asm volatile("tcgen05.wait::ld.sync.aligned;" ::: "memory");
    asm volatile("tcgen05.fence::before_thread_sync;" ::: "memory");

    float* Os = (float*)(smem + OFF_K0);          // 64 x 132 staging (K bufs dead)
    #pragma unroll
    for (int j = 0; j < 32; ++j)
        Os[(j0 + j) * 132 + rtid] = __uint_as_float(orr[j]) * inv;
    __syncthreads();
    float* obase = out + (size_t)bh * HD * NSEQ + q0;
    #pragma unroll
    for (int i = 0; i < 8; ++i) {
        int idx = tid + i * 256;
        int d = idx >> 5, q4 = (idx & 31) * 4;
        *(float4*)&obase[(size_t)d * NSEQ + q4] = *(float4*)&Os[d * 132 + q4];
    }
    __syncthreads();
    if (wid == 0)
        asm volatile("tcgen05.dealloc.cta_group::1.sync.aligned.b32 %0, %1;"
                     :: "r"(tb), "r"(256u));
#else
    // scalar fallback (non-103a pass only; correct, never runs)
    if (tid < 128) {
        const int qg = q0 + tid;
        const float* hq = hbase + (size_t)qg * HD;
        float o[HD];
        #pragma unroll
        for (int d = 0; d < HD; ++d) o[d] = 0.f;
        float l = 0.f;
        for (int k = 0; k <= qg; ++k) {
            const float* hk = hbase + (size_t)k * HD;
            float s = 0.f;
            #pragma unroll
            for (int d = 0; d < HD; ++d) s += hq[d] * hk[d];
            float pv = exp2f(s * sc2);
            l += pv;
            #pragma unroll
            for (int d = 0; d < HD; ++d) o[d] += pv * hk[d];
        }
        float* obase = out + (size_t)bh * HD * NSEQ + q0;
        float inv = 1.0f / l;
        #pragma unroll
        for (int d = 0; d < HD; ++d)
            obase[(size_t)d * NSEQ + tid] = o[d] * inv;
    }
#endif
}

// ---------------------------------------------------------------------------
extern "C" void kernel_launch(void* const* d_in, const int* in_sizes, int n_in,
                              void* d_out, int out_size) {
    const float* x  = (const float*)d_in[0];
    const float* Wq = (const float*)d_in[1];
    float* out = (float*)d_out;

    cudaFuncSetAttribute(qkv_gemm, cudaFuncAttributeMaxDynamicSharedMemorySize, GEMM_SMEM);
    cudaFuncSetAttribute(attn_kernel, cudaFuncAttributeMaxDynamicSharedMemorySize, ATTN_SMEM);

    round_inputs<<<1824, 256>>>(x, Wq);
    qkv_gemm<<<dim3(32, 12), 256, GEMM_SMEM>>>();
    attn_kernel<<<384, 256, ATTN_SMEM>>>(out);
}